// round 7
// baseline (speedup 1.0000x reference)
#include <cuda_runtime.h>
#include <cuda_bf16.h>
#include <math.h>
#include <stdint.h>

#define Bz 2
#define Tz 1024
#define Cz 1024
#define Hz 16
#define HDz 64
#define Lz 12
#define Vz 50257
#define BTz (Bz*Tz)
#define C4z (4*Cz)
#define C3z (3*Cz)

#define TEL 12288ULL      // bf16 elems per packed 128n x 32k tile (128*96)

// ---------------- scratch (device globals; no allocation) ----------------
__device__ float g_x[BTz*Cz];                       // residual (fp32)
__device__ float g_qkv[(size_t)BTz*C3z];            // QKV output (fp32, attn input)
__device__ float g_red[BTz];
__device__ float g_bpack[C3z];
__device__ __nv_bfloat16 g_hp [(size_t)BTz*C3z];    // LN output, packed hi/lo
__device__ __nv_bfloat16 g_yp [(size_t)BTz*C3z];    // attn output, packed
__device__ __nv_bfloat16 g_ffp[(size_t)BTz*3*C4z];  // MLP hidden, packed
// packed weights (tiled layout)
__device__ __nv_bfloat16 g_pQKV[Lz*768*TEL];
__device__ __nv_bfloat16 g_pWo [Lz*256*TEL];
__device__ __nv_bfloat16 g_pW1 [Lz*1024*TEL];
__device__ __nv_bfloat16 g_pW2 [Lz*1024*TEL];
__device__ __nv_bfloat16 g_pHead[12576*TEL];        // 393 n-tiles x 32 k-tiles

// ---------------- helpers ----------------
__device__ __forceinline__ uint32_t hilo32(float x) {
    __nv_bfloat16 h = __float2bfloat16(x);
    unsigned short hu = __bfloat16_as_ushort(h);
    unsigned short lu = __bfloat16_as_ushort(__float2bfloat16(x - __bfloat162float(h)));
    return (uint32_t)hu | ((uint32_t)lu << 16);
}
__device__ __forceinline__ unsigned short bfhi(float x) {
    return __bfloat16_as_ushort(__float2bfloat16(x));
}

__device__ __forceinline__ float blockReduceSum(float v) {
    __shared__ float sh[33];
    int lane = threadIdx.x & 31, w = threadIdx.x >> 5;
    #pragma unroll
    for (int o = 16; o; o >>= 1) v += __shfl_down_sync(0xffffffffu, v, o);
    __syncthreads();
    if (lane == 0) sh[w] = v;
    __syncthreads();
    if (threadIdx.x == 0) {
        float s = 0.f;
        int nw = blockDim.x >> 5;
        for (int i = 0; i < nw; i++) s += sh[i];
        sh[32] = s;
    }
    __syncthreads();
    return sh[32];
}

__device__ __forceinline__ float blockReduceMax(float v) {
    __shared__ float sh[33];
    int lane = threadIdx.x & 31, w = threadIdx.x >> 5;
    #pragma unroll
    for (int o = 16; o; o >>= 1) v = fmaxf(v, __shfl_down_sync(0xffffffffu, v, o));
    __syncthreads();
    if (lane == 0) sh[w] = v;
    __syncthreads();
    if (threadIdx.x == 0) {
        float s = -1e30f;
        int nw = blockDim.x >> 5;
        for (int i = 0; i < nw; i++) s = fmaxf(s, sh[i]);
        sh[32] = s;
    }
    __syncthreads();
    return sh[32];
}

// ---------------- embedding ----------------
__global__ void embed_kernel(const int* __restrict__ idx,
                             const float* __restrict__ tok,
                             const float* __restrict__ pos) {
    int r = blockIdx.x;
    int c = threadIdx.x * 4;
    int tokid = idx[r];
    float4 te = *(const float4*)(tok + (size_t)tokid * Cz + c);
    float4 pe = *(const float4*)(pos + (size_t)(r % Tz) * Cz + c);
    float4 o;
    o.x = te.x + pe.x; o.y = te.y + pe.y; o.z = te.z + pe.z; o.w = te.w + pe.w;
    *(float4*)(g_x + (size_t)r * Cz + c) = o;
}

// ---------------- layernorm -> packed hi/lo A ----------------
// row layout: [0,2C) = (hi,lo) interleaved, [2C,3C) = hi
__global__ void ln_pack_kernel(const float* __restrict__ x,
                               const float* __restrict__ w,
                               const float* __restrict__ b,
                               __nv_bfloat16* __restrict__ outp) {
    int r = blockIdx.x;
    const float* xr = x + (size_t)r * Cz;
    float v[4];
    #pragma unroll
    for (int k = 0; k < 4; k++) v[k] = xr[threadIdx.x + k * 256];
    float s = v[0] + v[1] + v[2] + v[3];
    s = blockReduceSum(s);
    float mu = s * (1.0f / Cz);
    float sq = 0.f;
    #pragma unroll
    for (int k = 0; k < 4; k++) { float d = v[k] - mu; sq += d * d; }
    sq = blockReduceSum(sq);
    float rstd = rsqrtf(sq * (1.0f / Cz) + 1e-5f);
    __nv_bfloat16* orow = outp + (size_t)r * C3z;
    #pragma unroll
    for (int k = 0; k < 4; k++) {
        int c = threadIdx.x + k * 256;
        float xv = (v[k] - mu) * rstd * w[c] + b[c];
        *(uint32_t*)(orow + 2 * c) = hilo32(xv);
        orow[2 * Cz + c] = __float2bfloat16(xv);
    }
}

// ---------------- weight pack: (K x N fp32) -> tiled [(bh,bh)x64 | bl x32] ----------------
template<bool GUARD>
__global__ void packB_kernel(const float* __restrict__ B,
                             __nv_bfloat16* __restrict__ dst, int N) {
    int cb = blockIdx.x, kt = blockIdx.y, Kt = gridDim.y;
    int n = threadIdx.x & 127, kh = threadIdx.x >> 7;
    int ng = cb * 128 + n;
    bool valid = (!GUARD) || (ng < N);
    const float* src = B + (size_t)(kt * 32 + kh * 16) * N + (valid ? ng : 0);
    __nv_bfloat16* d = dst + ((size_t)cb * Kt + kt) * TEL + n * 96;
    uint32_t inter[16]; unsigned short lo[16];
    #pragma unroll
    for (int j = 0; j < 16; j++) {
        float x = valid ? src[(size_t)j * N] : 0.f;
        __nv_bfloat16 hb = __float2bfloat16(x);
        unsigned short hu = __bfloat16_as_ushort(hb);
        lo[j] = __bfloat16_as_ushort(__float2bfloat16(x - __bfloat162float(hb)));
        inter[j] = (uint32_t)hu | ((uint32_t)hu << 16);
    }
    uint4* di = (uint4*)(d + 32 * kh);
    di[0] = ((const uint4*)inter)[0]; di[1] = ((const uint4*)inter)[1];
    di[2] = ((const uint4*)inter)[2]; di[3] = ((const uint4*)inter)[3];
    uint32_t lw[8];
    #pragma unroll
    for (int j = 0; j < 8; j++) lw[j] = (uint32_t)lo[2*j] | ((uint32_t)lo[2*j+1] << 16);
    uint4* dl = (uint4*)(d + 64 + 16 * kh);
    dl[0] = ((const uint4*)lw)[0]; dl[1] = ((const uint4*)lw)[1];
}

__global__ void packB_qkv_kernel(const float* __restrict__ Wq,
                                 const float* __restrict__ Wk,
                                 const float* __restrict__ Wv,
                                 __nv_bfloat16* __restrict__ dst) {
    int cb = blockIdx.x, kt = blockIdx.y;
    int n = threadIdx.x & 127, kh = threadIdx.x >> 7;
    int ng = cb * 128 + n;
    int which = ng >> 10, nl = ng & 1023;
    const float* src = ((which == 0) ? Wq : (which == 1) ? Wk : Wv)
                       + (size_t)(kt * 32 + kh * 16) * Cz + nl;
    __nv_bfloat16* d = dst + ((size_t)cb * 32 + kt) * TEL + n * 96;
    uint32_t inter[16]; unsigned short lo[16];
    #pragma unroll
    for (int j = 0; j < 16; j++) {
        float x = src[(size_t)j * Cz];
        __nv_bfloat16 hb = __float2bfloat16(x);
        unsigned short hu = __bfloat16_as_ushort(hb);
        lo[j] = __bfloat16_as_ushort(__float2bfloat16(x - __bfloat162float(hb)));
        inter[j] = (uint32_t)hu | ((uint32_t)hu << 16);
    }
    uint4* di = (uint4*)(d + 32 * kh);
    di[0] = ((const uint4*)inter)[0]; di[1] = ((const uint4*)inter)[1];
    di[2] = ((const uint4*)inter)[2]; di[3] = ((const uint4*)inter)[3];
    uint32_t lw[8];
    #pragma unroll
    for (int j = 0; j < 8; j++) lw[j] = (uint32_t)lo[2*j] | ((uint32_t)lo[2*j+1] << 16);
    uint4* dl = (uint4*)(d + 64 + 16 * kh);
    dl[0] = ((const uint4*)lw)[0]; dl[1] = ((const uint4*)lw)[1];
}

__global__ void pack_bias_kernel(const float* __restrict__ bq,
                                 const float* __restrict__ bk,
                                 const float* __restrict__ bv) {
    int which = blockIdx.x;
    const float* src = (which == 0) ? bq : (which == 1) ? bk : bv;
    int c = threadIdx.x * 4;
    float4 v = *(const float4*)(src + c);
    *(float4*)(g_bpack + which * Cz + c) = v;
}

// ---------------- mma / ldmatrix primitives ----------------
__device__ __forceinline__ void mma16816(float4& c, uint32_t a0, uint32_t a1,
                                         uint32_t a2, uint32_t a3,
                                         uint32_t b0, uint32_t b1) {
    asm volatile(
        "mma.sync.aligned.m16n8k16.row.col.f32.bf16.bf16.f32 "
        "{%0,%1,%2,%3}, {%4,%5,%6,%7}, {%8,%9}, {%0,%1,%2,%3};"
        : "+f"(c.x), "+f"(c.y), "+f"(c.z), "+f"(c.w)
        : "r"(a0), "r"(a1), "r"(a2), "r"(a3), "r"(b0), "r"(b1));
}

__device__ __forceinline__ void ldsm4(uint32_t& r0, uint32_t& r1,
                                      uint32_t& r2, uint32_t& r3, uint32_t addr) {
    asm volatile("ldmatrix.sync.aligned.m8n8.x4.shared.b16 {%0,%1,%2,%3}, [%4];"
        : "=r"(r0), "=r"(r1), "=r"(r2), "=r"(r3) : "r"(addr));
}

// =========================================================================
// Packed-input tensor-core GEMM. M fixed 2048. A: packed M x 3K rows.
// B: packed tiled [(N/128) x (K/32)] x (128x96). cp.async double buffer.
// EPI: 0=bias->f32, 1=bias+res->f32, 2=bias+gelu->packed, 3=plain->f32
// =========================================================================
#define MST 104
#define ATILE (128*MST)
#define TILEB (ATILE*2)
#define GSMEM (4*TILEB)

#define CPA(dst, src) asm volatile("cp.async.cg.shared.global [%0], [%1], 16;\n" :: "r"(dst), "l"(src))

template<int EPI, bool NGUARD>
__global__ void __launch_bounds__(256, 1)
gemm_pk_kernel(const __nv_bfloat16* __restrict__ Apack,
               const __nv_bfloat16* __restrict__ Bpack,
               const float* __restrict__ bias, const float* __restrict__ res,
               float* __restrict__ outF, __nv_bfloat16* __restrict__ outP,
               int N, int K) {
    extern __shared__ __nv_bfloat16 smem[];
    int tid = threadIdx.x, lane = tid & 31, warp = tid >> 5;
    int wm = warp & 1, wn = warp >> 1;
    int g = lane >> 2, tg = lane & 3;
    int rowBlk = blockIdx.y * 128, colBlk = blockIdx.x * 128;
    int row2 = tid >> 1, h2 = tid & 1;
    int t8 = lane >> 3, r8 = lane & 7;
    int aoff = ((t8 & 1) * 8 + r8) * MST + (t8 >> 1) * 8;
    int boff = ((t8 >> 1) * 8 + r8) * MST + (t8 & 1) * 8;
    uint32_t sbase = (uint32_t)__cvta_generic_to_shared(smem);

    const __nv_bfloat16* aBase = Apack + (size_t)(rowBlk + row2) * (3 * K);
    const __nv_bfloat16* bBase = Bpack + (size_t)blockIdx.x * (K / 32) * TEL + row2 * 96;

    float4 acc[4][4];
    #pragma unroll
    for (int i = 0; i < 4; i++)
        #pragma unroll
        for (int j = 0; j < 4; j++) acc[i][j] = make_float4(0.f, 0.f, 0.f, 0.f);

#define PREF(s, kt) { \
        uint32_t ai = sbase + (s) * (2 * TILEB) + (uint32_t)(row2 * MST + 32 * h2) * 2; \
        const __nv_bfloat16* sI = aBase + 64 * (kt) + 32 * h2; \
        CPA(ai,      sI);      CPA(ai + 16, sI + 8); \
        CPA(ai + 32, sI + 16); CPA(ai + 48, sI + 24); \
        uint32_t ah = sbase + (s) * (2 * TILEB) + (uint32_t)(row2 * MST + 64 + 16 * h2) * 2; \
        const __nv_bfloat16* sH = aBase + 2 * K + 32 * (kt) + 16 * h2; \
        CPA(ah, sH); CPA(ah + 16, sH + 8); \
        const __nv_bfloat16* bT = bBase + (size_t)(kt) * TEL; \
        uint32_t bi = sbase + (s) * (2 * TILEB) + TILEB + (uint32_t)(row2 * MST + 32 * h2) * 2; \
        const __nv_bfloat16* sBI = bT + 32 * h2; \
        CPA(bi,      sBI);      CPA(bi + 16, sBI + 8); \
        CPA(bi + 32, sBI + 16); CPA(bi + 48, sBI + 24); \
        uint32_t bh = sbase + (s) * (2 * TILEB) + TILEB + (uint32_t)(row2 * MST + 64 + 16 * h2) * 2; \
        const __nv_bfloat16* sBH = bT + 64 + 16 * h2; \
        CPA(bh, sBH); CPA(bh + 16, sBH + 8); \
        asm volatile("cp.async.commit_group;\n"); }

#define MMAS(s) { uint32_t Ab = sbase + (s) * (2 * TILEB); \
        uint32_t Bb = sbase + TILEB + (s) * (2 * TILEB); \
        _Pragma("unroll") \
        for (int ks = 0; ks < 6; ks++) { \
            int kb = ks * 16; \
            uint32_t ra[4][4], rb[4][2]; \
            _Pragma("unroll") \
            for (int mf = 0; mf < 4; mf++) \
                ldsm4(ra[mf][0], ra[mf][1], ra[mf][2], ra[mf][3], \
                      Ab + 2u * (uint32_t)((wm * 64 + mf * 16) * MST + aoff + kb)); \
            _Pragma("unroll") \
            for (int p = 0; p < 2; p++) \
                ldsm4(rb[2*p][0], rb[2*p][1], rb[2*p+1][0], rb[2*p+1][1], \
                      Bb + 2u * (uint32_t)((wn * 32 + p * 16) * MST + boff + kb)); \
            _Pragma("unroll") \
            for (int mf = 0; mf < 4; mf++) \
                _Pragma("unroll") \
                for (int nf = 0; nf < 4; nf++) \
                    mma16816(acc[mf][nf], ra[mf][0], ra[mf][1], ra[mf][2], ra[mf][3], \
                             rb[nf][0], rb[nf][1]); } }

    int nt = K / 32;
    PREF(0, 0);
    for (int kt = 0; kt < nt; kt++) {
        int s = kt & 1;
        if (kt + 1 < nt) {
            PREF(s ^ 1, kt + 1);
            asm volatile("cp.async.wait_group 1;\n" ::: "memory");
        } else {
            asm volatile("cp.async.wait_group 0;\n" ::: "memory");
        }
        __syncthreads();
        MMAS(s);
        __syncthreads();
    }

    // ---- epilogue ----
    #pragma unroll
    for (int mf = 0; mf < 4; mf++) {
        int row0 = rowBlk + wm * 64 + mf * 16 + g;
        #pragma unroll
        for (int nf = 0; nf < 4; nf++) {
            int col = colBlk + wn * 32 + nf * 8 + tg * 2;
            float vals[4] = {acc[mf][nf].x, acc[mf][nf].y, acc[mf][nf].z, acc[mf][nf].w};
            #pragma unroll
            for (int h = 0; h < 2; h++) {
                int row = row0 + h * 8;
                float v0 = vals[h * 2], v1 = vals[h * 2 + 1];
                if (EPI == 0 || EPI == 1 || EPI == 2) {
                    v0 += bias[col]; v1 += bias[col + 1];
                }
                if (EPI == 2) {
                    v0 = 0.5f * v0 * (1.0f + erff(v0 * 0.7071067811865476f));
                    v1 = 0.5f * v1 * (1.0f + erff(v1 * 0.7071067811865476f));
                }
                if (EPI == 1) {
                    v0 += res[(size_t)row * N + col];
                    v1 += res[(size_t)row * N + col + 1];
                }
                if (EPI == 2) {
                    size_t rowb = (size_t)row * (size_t)(3 * N);
                    *(uint2*)(outP + rowb + 2 * col) = make_uint2(hilo32(v0), hilo32(v1));
                    *(uint32_t*)(outP + rowb + 2 * N + col) =
                        (uint32_t)bfhi(v0) | ((uint32_t)bfhi(v1) << 16);
                } else {
                    if (!NGUARD || col < N)     outF[(size_t)row * N + col] = v0;
                    if (!NGUARD || col + 1 < N) outF[(size_t)row * N + col + 1] = v1;
                }
            }
        }
    }
#undef PREF
#undef MMAS
}

// =========================================================================
// Fused flash attention (unchanged math; epilogue writes packed g_yp)
// =========================================================================
#define FA_QST 200
#define FA_KST 200
#define FA_VST 136
#define FA_SMEM ((64*FA_QST + 64*FA_KST + 64*FA_VST)*2)

__global__ void __launch_bounds__(128, 2)
attn_fused_kernel() {
    extern __shared__ __nv_bfloat16 sm[];
    __nv_bfloat16* Qs = sm;
    __nv_bfloat16* Ks = sm + 64 * FA_QST;
    __nv_bfloat16* Vs = sm + 64 * (FA_QST + FA_KST);
    int tid = threadIdx.x, lane = tid & 31, warp = tid >> 5;
    int qt = blockIdx.x, bh = blockIdx.y;
    int b = bh >> 4, h = bh & 15;
    int g = lane >> 2, tg = lane & 3;
    int t8 = lane >> 3, r8 = lane & 7;
    uint32_t sb = (uint32_t)__cvta_generic_to_shared(sm);
    uint32_t Qb = sb;
    uint32_t Kb = sb + 64 * FA_QST * 2;
    uint32_t Vb = sb + 64 * (FA_QST + FA_KST) * 2;
    int aoff = ((t8 & 1) * 8 + r8) * FA_QST + (t8 >> 1) * 8;
    int koff = ((t8 >> 1) * 8 + r8) * FA_KST + (t8 & 1) * 8;
    int voff = ((t8 >> 1) * 8 + r8) * FA_VST + (t8 & 1) * 8;

    {
        int row = tid >> 1, seg = (tid & 1) * 32;
        const float* src = g_qkv + (size_t)(b * Tz + qt * 64 + row) * C3z + h * HDz + seg;
        uint32_t wbuf[32]; unsigned short hsb[32];
        #pragma unroll
        for (int i = 0; i < 8; i++) {
            float4 v = *(const float4*)(src + i * 4);
            float xs[4] = {v.x, v.y, v.z, v.w};
            #pragma unroll
            for (int e = 0; e < 4; e++) {
                float x = xs[e] * 0.125f;
                __nv_bfloat16 hb = __float2bfloat16(x);
                __nv_bfloat16 lb = __float2bfloat16(x - __bfloat162float(hb));
                int i4 = i * 4 + e;
                wbuf[i4] = (uint32_t)__bfloat16_as_ushort(hb) |
                           ((uint32_t)__bfloat16_as_ushort(lb) << 16);
                hsb[i4] = __bfloat16_as_ushort(hb);
            }
        }
        uint4* d0 = (uint4*)(Qs + row * FA_QST + 2 * seg);
        #pragma unroll
        for (int i = 0; i < 8; i++) d0[i] = ((const uint4*)wbuf)[i];
        uint32_t hw[16];
        #pragma unroll
        for (int j = 0; j < 16; j++)
            hw[j] = (uint32_t)hsb[2 * j] | ((uint32_t)hsb[2 * j + 1] << 16);
        uint4* d1 = (uint4*)(Qs + row * FA_QST + 128 + seg);
        #pragma unroll
        for (int i = 0; i < 4; i++) d1[i] = ((const uint4*)hw)[i];
    }

    float m0 = -1e30f, m1 = -1e30f, l0 = 0.f, l1 = 0.f;
    float4 O[8];
    #pragma unroll
    for (int i = 0; i < 8; i++) O[i] = make_float4(0.f, 0.f, 0.f, 0.f);

    for (int kt = 0; kt <= qt; kt++) {
        {
            int row = tid >> 1, seg = (tid & 1) * 32;
            const float* src = g_qkv + (size_t)(b * Tz + kt * 64 + row) * C3z + Cz + h * HDz + seg;
            uint32_t wbuf[32]; unsigned short lsb[32];
            #pragma unroll
            for (int i = 0; i < 8; i++) {
                float4 v = *(const float4*)(src + i * 4);
                float xs[4] = {v.x, v.y, v.z, v.w};
                #pragma unroll
                for (int e = 0; e < 4; e++) {
                    float x = xs[e];
                    __nv_bfloat16 hb = __float2bfloat16(x);
                    unsigned short hu = __bfloat16_as_ushort(hb);
                    __nv_bfloat16 lb = __float2bfloat16(x - __bfloat162float(hb));
                    int i4 = i * 4 + e;
                    wbuf[i4] = (uint32_t)hu | ((uint32_t)hu << 16);
                    lsb[i4] = __bfloat16_as_ushort(lb);
                }
            }
            uint4* d0 = (uint4*)(Ks + row * FA_KST + 2 * seg);
            #pragma unroll
            for (int i = 0; i < 8; i++) d0[i] = ((const uint4*)wbuf)[i];
            uint32_t lw[16];
            #pragma unroll
            for (int j = 0; j < 16; j++)
                lw[j] = (uint32_t)lsb[2 * j] | ((uint32_t)lsb[2 * j + 1] << 16);
            uint4* d1 = (uint4*)(Ks + row * FA_KST + 128 + seg);
            #pragma unroll
            for (int i = 0; i < 4; i++) d1[i] = ((const uint4*)lw)[i];
        }
        {
            int nd = (tid & 15) * 4;
            int k8 = (tid >> 4) * 8;
            unsigned short vh[4][8], vl[4][8];
            #pragma unroll
            for (int kk = 0; kk < 8; kk++) {
                const float* src = g_qkv + (size_t)(b * Tz + kt * 64 + k8 + kk) * C3z + 2 * Cz + h * HDz + nd;
                float4 v = *(const float4*)src;
                float xs[4] = {v.x, v.y, v.z, v.w};
                #pragma unroll
                for (int e = 0; e < 4; e++) {
                    float x = xs[e];
                    __nv_bfloat16 hb = __float2bfloat16(x);
                    __nv_bfloat16 lb = __float2bfloat16(x - __bfloat162float(hb));
                    vh[e][kk] = __bfloat16_as_ushort(hb);
                    vl[e][kk] = __bfloat16_as_ushort(lb);
                }
            }
            #pragma unroll
            for (int e = 0; e < 4; e++) {
                *(uint4*)(Vs + (nd + e) * FA_VST + k8)      = *(const uint4*)vh[e];
                *(uint4*)(Vs + (nd + e) * FA_VST + 64 + k8) = *(const uint4*)vl[e];
            }
        }
        __syncthreads();

        float4 S[8];
        #pragma unroll
        for (int i = 0; i < 8; i++) S[i] = make_float4(0.f, 0.f, 0.f, 0.f);
        #pragma unroll
        for (int ks = 0; ks < 12; ks++) {
            int kb = ks * 16;
            uint32_t ra0, ra1, ra2, ra3;
            ldsm4(ra0, ra1, ra2, ra3, Qb + 2u * (uint32_t)(warp * 16 * FA_QST + aoff + kb));
            #pragma unroll
            for (int pp = 0; pp < 4; pp++) {
                uint32_t b0, b1, b2, b3;
                ldsm4(b0, b1, b2, b3, Kb + 2u * (uint32_t)((pp * 16) * FA_KST + koff + kb));
                mma16816(S[2 * pp],     ra0, ra1, ra2, ra3, b0, b1);
                mma16816(S[2 * pp + 1], ra0, ra1, ra2, ra3, b2, b3);
            }
        }

        if (kt == qt) {
            int r0 = warp * 16 + g, r1 = r0 + 8;
            #pragma unroll
            for (int j = 0; j < 8; j++) {
                int c0 = j * 8 + 2 * tg, c1 = c0 + 1;
                if (c0 > r0) S[j].x = -1e30f;
                if (c1 > r0) S[j].y = -1e30f;
                if (c0 > r1) S[j].z = -1e30f;
                if (c1 > r1) S[j].w = -1e30f;
            }
        }

        float mx0 = -1e30f, mx1 = -1e30f;
        #pragma unroll
        for (int j = 0; j < 8; j++) {
            mx0 = fmaxf(mx0, fmaxf(S[j].x, S[j].y));
            mx1 = fmaxf(mx1, fmaxf(S[j].z, S[j].w));
        }
        mx0 = fmaxf(mx0, __shfl_xor_sync(0xffffffffu, mx0, 1));
        mx0 = fmaxf(mx0, __shfl_xor_sync(0xffffffffu, mx0, 2));
        mx1 = fmaxf(mx1, __shfl_xor_sync(0xffffffffu, mx1, 1));
        mx1 = fmaxf(mx1, __shfl_xor_sync(0xffffffffu, mx1, 2));
        float mn0 = fmaxf(m0, mx0), mn1 = fmaxf(m1, mx1);
        float al0 = __expf(m0 - mn0), al1 = __expf(m1 - mn1);
        m0 = mn0; m1 = mn1;
        float rs0 = 0.f, rs1 = 0.f;
        #pragma unroll
        for (int j = 0; j < 8; j++) {
            S[j].x = __expf(S[j].x - m0);
            S[j].y = __expf(S[j].y - m0);
            S[j].z = __expf(S[j].z - m1);
            S[j].w = __expf(S[j].w - m1);
            rs0 += S[j].x + S[j].y;
            rs1 += S[j].z + S[j].w;
        }
        rs0 += __shfl_xor_sync(0xffffffffu, rs0, 1);
        rs0 += __shfl_xor_sync(0xffffffffu, rs0, 2);
        rs1 += __shfl_xor_sync(0xffffffffu, rs1, 1);
        rs1 += __shfl_xor_sync(0xffffffffu, rs1, 2);
        l0 = l0 * al0 + rs0;
        l1 = l1 * al1 + rs1;
        #pragma unroll
        for (int j = 0; j < 8; j++) {
            O[j].x *= al0; O[j].y *= al0;
            O[j].z *= al1; O[j].w *= al1;
        }

        #pragma unroll
        for (int kc = 0; kc < 4; kc++) {
            float4 s0 = S[2 * kc], s1 = S[2 * kc + 1];
            float f0[8] = {s0.x, s0.y, s0.z, s0.w, s1.x, s1.y, s1.z, s1.w};
            unsigned short phs[8], pls[8];
            #pragma unroll
            for (int e = 0; e < 8; e++) {
                __nv_bfloat16 hb = __float2bfloat16(f0[e]);
                phs[e] = __bfloat16_as_ushort(hb);
                pls[e] = __bfloat16_as_ushort(__float2bfloat16(f0[e] - __bfloat162float(hb)));
            }
            uint32_t ph0 = (uint32_t)phs[0] | ((uint32_t)phs[1] << 16);
            uint32_t ph1 = (uint32_t)phs[2] | ((uint32_t)phs[3] << 16);
            uint32_t ph2 = (uint32_t)phs[4] | ((uint32_t)phs[5] << 16);
            uint32_t ph3 = (uint32_t)phs[6] | ((uint32_t)phs[7] << 16);
            uint32_t pl0 = (uint32_t)pls[0] | ((uint32_t)pls[1] << 16);
            uint32_t pl1 = (uint32_t)pls[2] | ((uint32_t)pls[3] << 16);
            uint32_t pl2 = (uint32_t)pls[4] | ((uint32_t)pls[5] << 16);
            uint32_t pl3 = (uint32_t)pls[6] | ((uint32_t)pls[7] << 16);

            uint32_t vh[8][2], vl[8][2];
            #pragma unroll
            for (int pp = 0; pp < 4; pp++) {
                ldsm4(vh[2*pp][0], vh[2*pp][1], vh[2*pp+1][0], vh[2*pp+1][1],
                      Vb + 2u * (uint32_t)((pp * 16) * FA_VST + voff + kc * 16));
                ldsm4(vl[2*pp][0], vl[2*pp][1], vl[2*pp+1][0], vl[2*pp+1][1],
                      Vb + 2u * (uint32_t)((pp * 16) * FA_VST + voff + 64 + kc * 16));
            }
            #pragma unroll
            for (int nf = 0; nf < 8; nf++) {
                mma16816(O[nf], ph0, ph1, ph2, ph3, vh[nf][0], vh[nf][1]);
                mma16816(O[nf], pl0, pl1, pl2, pl3, vh[nf][0], vh[nf][1]);
                mma16816(O[nf], ph0, ph1, ph2, ph3, vl[nf][0], vl[nf][1]);
            }
        }
        __syncthreads();
    }

    // ---- finalize: write packed g_yp ----
    float i0 = 1.0f / l0, i1 = 1.0f / l1;
    int qrow = qt * 64 + warp * 16 + g;
    size_t rb0 = (size_t)(b * Tz + qrow) * C3z;
    size_t rb1 = (size_t)(b * Tz + qrow + 8) * C3z;
    #pragma unroll
    for (int nf = 0; nf < 8; nf++) {
        int colg = h * HDz + nf * 8 + 2 * tg;
        float vx = O[nf].x * i0, vy = O[nf].y * i0;
        float wx = O[nf].z * i1, wy = O[nf].w * i1;
        *(uint2*)(g_yp + rb0 + 2 * colg) = make_uint2(hilo32(vx), hilo32(vy));
        *(uint32_t*)(g_yp + rb0 + 2 * Cz + colg) = (uint32_t)bfhi(vx) | ((uint32_t)bfhi(vy) << 16);
        *(uint2*)(g_yp + rb1 + 2 * colg) = make_uint2(hilo32(wx), hilo32(wy));
        *(uint32_t*)(g_yp + rb1 + 2 * Cz + colg) = (uint32_t)bfhi(wx) | ((uint32_t)bfhi(wy) << 16);
    }
}

// ---------------- loss ----------------
__global__ void loss_row_kernel(const float* __restrict__ logits,
                                const int* __restrict__ targets) {
    int r = blockIdx.x;
    const float* row = logits + (size_t)r * Vz;
    int tid = threadIdx.x;
    float mx = -1e30f;
    for (int j = tid; j < Vz; j += 256) mx = fmaxf(mx, row[j]);
    mx = blockReduceMax(mx);
    float s = 0.f;
    for (int j = tid; j < Vz; j += 256) s += expf(row[j] - mx);
    s = blockReduceSum(s);
    if (tid == 0) {
        int t = targets[r];
        g_red[r] = -(row[t] - mx - logf(s));
    }
}

__global__ void loss_final_kernel(float* __restrict__ out, int out_size) {
    int tid = threadIdx.x;
    float s = 0.f;
    for (int j = tid; j < BTz; j += 256) s += g_red[j];
    s = blockReduceSum(s);
    if (tid == 0) {
        long long logits_elems = (long long)BTz * Vz;
        if ((long long)out_size > logits_elems)
            out[logits_elems] = s / (float)BTz;
    }
}

// ---------------- launch ----------------
extern "C" void kernel_launch(void* const* d_in, const int* in_sizes, int n_in,
                              void* d_out, int out_size) {
    const int*   idx     = (const int*)d_in[0];
    const int*   targets = (const int*)d_in[1];
    const float* tok_emb = (const float*)d_in[2];
    const float* pos_emb = (const float*)d_in[3];
    const float* ln1_w   = (const float*)d_in[4];
    const float* ln1_b   = (const float*)d_in[5];
    const float* ln2_w   = (const float*)d_in[6];
    const float* ln2_b   = (const float*)d_in[7];
    const float* Wq = (const float*)d_in[8];
    const float* bq = (const float*)d_in[9];
    const float* Wk = (const float*)d_in[10];
    const float* bk = (const float*)d_in[11];
    const float* Wv = (const float*)d_in[12];
    const float* bv = (const float*)d_in[13];
    const float* Wo = (const float*)d_in[14];
    const float* bo = (const float*)d_in[15];
    const float* W1 = (const float*)d_in[16];
    const float* b1 = (const float*)d_in[17];
    const float* W2 = (const float*)d_in[18];
    const float* b2 = (const float*)d_in[19];
    const float* lnf_w  = (const float*)d_in[20];
    const float* lnf_b  = (const float*)d_in[21];
    const float* head_w = (const float*)d_in[22];
    float* out = (float*)d_out;

    float *px, *pbp;
    __nv_bfloat16 *php, *pffp, *pyp, *pQKVw, *pWow, *pW1w, *pW2w, *pHeadw;
    cudaGetSymbolAddress((void**)&px,    g_x);
    cudaGetSymbolAddress((void**)&pbp,   g_bpack);
    cudaGetSymbolAddress((void**)&php,   g_hp);
    cudaGetSymbolAddress((void**)&pffp,  g_ffp);
    cudaGetSymbolAddress((void**)&pyp,   g_yp);
    cudaGetSymbolAddress((void**)&pQKVw, g_pQKV);
    cudaGetSymbolAddress((void**)&pWow,  g_pWo);
    cudaGetSymbolAddress((void**)&pW1w,  g_pW1);
    cudaGetSymbolAddress((void**)&pW2w,  g_pW2);
    cudaGetSymbolAddress((void**)&pHeadw,g_pHead);
    float* pqkv;
    cudaGetSymbolAddress((void**)&pqkv,  g_qkv);

    cudaFuncSetAttribute(gemm_pk_kernel<0, false>, cudaFuncAttributeMaxDynamicSharedMemorySize, GSMEM);
    cudaFuncSetAttribute(gemm_pk_kernel<1, false>, cudaFuncAttributeMaxDynamicSharedMemorySize, GSMEM);
    cudaFuncSetAttribute(gemm_pk_kernel<2, false>, cudaFuncAttributeMaxDynamicSharedMemorySize, GSMEM);
    cudaFuncSetAttribute(gemm_pk_kernel<3, true >, cudaFuncAttributeMaxDynamicSharedMemorySize, GSMEM);
    cudaFuncSetAttribute(attn_fused_kernel, cudaFuncAttributeMaxDynamicSharedMemorySize, FA_SMEM);

    const size_t CC  = (size_t)Cz * Cz;
    const size_t C14 = (size_t)Cz * C4z;

    // ---- pack all weights ----
    for (int l = 0; l < Lz; l++) {
        packB_qkv_kernel<<<dim3(24, 32), 256>>>(Wq + l * CC, Wk + l * CC, Wv + l * CC,
                                                pQKVw + (size_t)l * 768 * TEL);
        packB_kernel<false><<<dim3(8, 32), 256>>>(Wo + l * CC, pWow + (size_t)l * 256 * TEL, Cz);
        packB_kernel<false><<<dim3(32, 32), 256>>>(W1 + l * C14, pW1w + (size_t)l * 1024 * TEL, C4z);
        packB_kernel<false><<<dim3(8, 128), 256>>>(W2 + l * C14, pW2w + (size_t)l * 1024 * TEL, Cz);
    }
    packB_kernel<true><<<dim3(393, 32), 256>>>(head_w, pHeadw, Vz);

    embed_kernel<<<BTz, 256>>>(idx, tok_emb, pos_emb);

    dim3 gQKV(24, 16), gCC(8, 16), gC4(32, 16), gHead(393, 16);

    for (int l = 0; l < Lz; l++) {
        pack_bias_kernel<<<3, 256>>>(bq + (size_t)l * Cz, bk + (size_t)l * Cz, bv + (size_t)l * Cz);
        ln_pack_kernel<<<BTz, 256>>>(px, ln1_w + (size_t)l * Cz, ln1_b + (size_t)l * Cz, php);
        gemm_pk_kernel<0, false><<<gQKV, 256, GSMEM>>>(php, pQKVw + (size_t)l * 768 * TEL,
                                                       pbp, nullptr, pqkv, nullptr, C3z, Cz);
        attn_fused_kernel<<<dim3(Tz / 64, Bz * Hz), 128, FA_SMEM>>>();
        gemm_pk_kernel<1, false><<<gCC, 256, GSMEM>>>(pyp, pWow + (size_t)l * 256 * TEL,
                                                      bo + (size_t)l * Cz, px, px, nullptr, Cz, Cz);
        ln_pack_kernel<<<BTz, 256>>>(px, ln2_w + (size_t)l * Cz, ln2_b + (size_t)l * Cz, php);
        gemm_pk_kernel<2, false><<<gC4, 256, GSMEM>>>(php, pW1w + (size_t)l * 1024 * TEL,
                                                      b1 + (size_t)l * C4z, nullptr, nullptr, pffp, C4z, Cz);
        gemm_pk_kernel<1, false><<<gCC, 256, GSMEM>>>(pffp, pW2w + (size_t)l * 1024 * TEL,
                                                      b2 + (size_t)l * Cz, px, px, nullptr, Cz, C4z);
    }

    ln_pack_kernel<<<BTz, 256>>>(px, lnf_w, lnf_b, php);
    gemm_pk_kernel<3, true><<<gHead, 256, GSMEM>>>(php, pHeadw, nullptr, nullptr, out, nullptr, Vz, Cz);
    loss_row_kernel<<<BTz, 256>>>(out, targets);
    loss_final_kernel<<<1, 256>>>(out, out_size);
}

// round 8
// speedup vs baseline: 1.2349x; 1.2349x over previous
#include <cuda_runtime.h>
#include <cuda_bf16.h>
#include <math.h>
#include <stdint.h>

#define Bz 2
#define Tz 1024
#define Cz 1024
#define Hz 16
#define HDz 64
#define Lz 12
#define Vz 50257
#define BTz (Bz*Tz)
#define C4z (4*Cz)
#define C3z (3*Cz)

// ---------------- scratch (device globals; no allocation) ----------------
__device__ float g_x[BTz*Cz];                       // residual (fp32)
__device__ float g_qkv[(size_t)BTz*C3z];            // QKV output (fp32, attn input)
__device__ float g_red[BTz];
__device__ float g_bpack[C3z];
__device__ float g_wpack[(size_t)Cz*C3z];           // QKV weights concat (fp32)
__device__ __nv_bfloat16 g_hp [(size_t)BTz*C3z];    // LN output, packed hi/lo
__device__ __nv_bfloat16 g_yp [(size_t)BTz*C3z];    // attn output, packed
__device__ __nv_bfloat16 g_ffp[(size_t)BTz*3*C4z];  // MLP hidden, packed

// ---------------- helpers ----------------
__device__ __forceinline__ uint32_t hilo32(float x) {
    __nv_bfloat16 h = __float2bfloat16(x);
    unsigned short hu = __bfloat16_as_ushort(h);
    unsigned short lu = __bfloat16_as_ushort(__float2bfloat16(x - __bfloat162float(h)));
    return (uint32_t)hu | ((uint32_t)lu << 16);
}
__device__ __forceinline__ unsigned short bfhi(float x) {
    return __bfloat16_as_ushort(__float2bfloat16(x));
}

__device__ __forceinline__ float blockReduceSum(float v) {
    __shared__ float sh[33];
    int lane = threadIdx.x & 31, w = threadIdx.x >> 5;
    #pragma unroll
    for (int o = 16; o; o >>= 1) v += __shfl_down_sync(0xffffffffu, v, o);
    __syncthreads();
    if (lane == 0) sh[w] = v;
    __syncthreads();
    if (threadIdx.x == 0) {
        float s = 0.f;
        int nw = blockDim.x >> 5;
        for (int i = 0; i < nw; i++) s += sh[i];
        sh[32] = s;
    }
    __syncthreads();
    return sh[32];
}

__device__ __forceinline__ float blockReduceMax(float v) {
    __shared__ float sh[33];
    int lane = threadIdx.x & 31, w = threadIdx.x >> 5;
    #pragma unroll
    for (int o = 16; o; o >>= 1) v = fmaxf(v, __shfl_down_sync(0xffffffffu, v, o));
    __syncthreads();
    if (lane == 0) sh[w] = v;
    __syncthreads();
    if (threadIdx.x == 0) {
        float s = -1e30f;
        int nw = blockDim.x >> 5;
        for (int i = 0; i < nw; i++) s = fmaxf(s, sh[i]);
        sh[32] = s;
    }
    __syncthreads();
    return sh[32];
}

// ---------------- embedding ----------------
__global__ void embed_kernel(const int* __restrict__ idx,
                             const float* __restrict__ tok,
                             const float* __restrict__ pos) {
    int r = blockIdx.x;
    int c = threadIdx.x * 4;
    int tokid = idx[r];
    float4 te = *(const float4*)(tok + (size_t)tokid * Cz + c);
    float4 pe = *(const float4*)(pos + (size_t)(r % Tz) * Cz + c);
    float4 o;
    o.x = te.x + pe.x; o.y = te.y + pe.y; o.z = te.z + pe.z; o.w = te.w + pe.w;
    *(float4*)(g_x + (size_t)r * Cz + c) = o;
}

// ---------------- layernorm -> packed hi/lo A ----------------
// row layout: [0,2C) = (hi,lo) interleaved, [2C,3C) = hi
__global__ void ln_pack_kernel(const float* __restrict__ x,
                               const float* __restrict__ w,
                               const float* __restrict__ b,
                               __nv_bfloat16* __restrict__ outp) {
    int r = blockIdx.x;
    const float* xr = x + (size_t)r * Cz;
    float v[4];
    #pragma unroll
    for (int k = 0; k < 4; k++) v[k] = xr[threadIdx.x + k * 256];
    float s = v[0] + v[1] + v[2] + v[3];
    s = blockReduceSum(s);
    float mu = s * (1.0f / Cz);
    float sq = 0.f;
    #pragma unroll
    for (int k = 0; k < 4; k++) { float d = v[k] - mu; sq += d * d; }
    sq = blockReduceSum(sq);
    float rstd = rsqrtf(sq * (1.0f / Cz) + 1e-5f);
    __nv_bfloat16* orow = outp + (size_t)r * C3z;
    #pragma unroll
    for (int k = 0; k < 4; k++) {
        int c = threadIdx.x + k * 256;
        float xv = (v[k] - mu) * rstd * w[c] + b[c];
        *(uint32_t*)(orow + 2 * c) = hilo32(xv);
        orow[2 * Cz + c] = __float2bfloat16(xv);
    }
}

// ---------------- QKV weight/bias packing (fp32 concat, cheap) ----------------
__global__ void pack_w_kernel(const float* __restrict__ Wq,
                              const float* __restrict__ Wk,
                              const float* __restrict__ Wv) {
    int which = blockIdx.y;
    const float* src = (which == 0) ? Wq : (which == 1) ? Wk : Wv;
    int k = blockIdx.x;
    int c = threadIdx.x * 4;
    float4 v = *(const float4*)(src + (size_t)k * Cz + c);
    *(float4*)(g_wpack + (size_t)k * C3z + which * Cz + c) = v;
}

__global__ void pack_bias_kernel(const float* __restrict__ bq,
                                 const float* __restrict__ bk,
                                 const float* __restrict__ bv) {
    int which = blockIdx.x;
    const float* src = (which == 0) ? bq : (which == 1) ? bk : bv;
    int c = threadIdx.x * 4;
    float4 v = *(const float4*)(src + c);
    *(float4*)(g_bpack + which * Cz + c) = v;
}

// ---------------- mma / ldmatrix primitives ----------------
__device__ __forceinline__ void mma16816(float4& c, uint32_t a0, uint32_t a1,
                                         uint32_t a2, uint32_t a3,
                                         uint32_t b0, uint32_t b1) {
    asm volatile(
        "mma.sync.aligned.m16n8k16.row.col.f32.bf16.bf16.f32 "
        "{%0,%1,%2,%3}, {%4,%5,%6,%7}, {%8,%9}, {%0,%1,%2,%3};"
        : "+f"(c.x), "+f"(c.y), "+f"(c.z), "+f"(c.w)
        : "r"(a0), "r"(a1), "r"(a2), "r"(a3), "r"(b0), "r"(b1));
}

__device__ __forceinline__ void ldsm4(uint32_t& r0, uint32_t& r1,
                                      uint32_t& r2, uint32_t& r3, uint32_t addr) {
    asm volatile("ldmatrix.sync.aligned.m8n8.x4.shared.b16 {%0,%1,%2,%3}, [%4];"
        : "=r"(r0), "=r"(r1), "=r"(r2), "=r"(r3) : "r"(addr));
}

// =========================================================================
// GEMM: A packed (cp.async, no convert), B fp32 (LDG + in-kernel convert).
// 128x128 tile, K-tile 32 fp32 (K''=96), single-sync double buffer.
// EPI: 0=bias->f32, 1=bias+res->f32, 2=bias+gelu->packed, 3=plain->f32
// =========================================================================
#define MST 104
#define ATILE (128*MST)
#define TILEB (ATILE*2)
#define GSMEM (4*TILEB)

#define CPA(dst, src) asm volatile("cp.async.cg.shared.global [%0], [%1], 16;\n" :: "r"(dst), "l"(src))

template<int EPI, bool NGUARD>
__global__ void __launch_bounds__(256, 1)
gemm_pk_kernel(const __nv_bfloat16* __restrict__ Apack,
               const float* __restrict__ Bm,
               const float* __restrict__ bias, const float* __restrict__ res,
               float* __restrict__ outF, __nv_bfloat16* __restrict__ outP,
               int N, int K) {
    extern __shared__ __nv_bfloat16 smem[];
    int tid = threadIdx.x, lane = tid & 31, warp = tid >> 5;
    int wm = warp & 1, wn = warp >> 1;
    int g = lane >> 2, tg = lane & 3;
    int rowBlk = blockIdx.y * 128, colBlk = blockIdx.x * 128;
    int row2 = tid >> 1, h2 = tid & 1;
    int bn = tid & 127, bseg = tid >> 7;
    int t8 = lane >> 3, r8 = lane & 7;
    int aoff = ((t8 & 1) * 8 + r8) * MST + (t8 >> 1) * 8;
    int boff = ((t8 >> 1) * 8 + r8) * MST + (t8 & 1) * 8;
    uint32_t sbase = (uint32_t)__cvta_generic_to_shared(smem);

    const __nv_bfloat16* aBase = Apack + (size_t)(rowBlk + row2) * (3 * K);
    int nb = colBlk + bn;
    bool bValid = (!NGUARD) || (nb < N);
    const float* bPtr = Bm + (size_t)bseg * 16 * N + (bValid ? nb : 0);

    float fb[16];
    float4 acc[4][4];
    #pragma unroll
    for (int i = 0; i < 4; i++)
        #pragma unroll
        for (int j = 0; j < 4; j++) acc[i][j] = make_float4(0.f, 0.f, 0.f, 0.f);

#define PREFA(s, kt) { \
        uint32_t ai = sbase + (s) * (2 * TILEB) + (uint32_t)(row2 * MST + 32 * h2) * 2; \
        const __nv_bfloat16* sI = aBase + 64 * (kt) + 32 * h2; \
        CPA(ai,      sI);      CPA(ai + 16, sI + 8); \
        CPA(ai + 32, sI + 16); CPA(ai + 48, sI + 24); \
        uint32_t ah = sbase + (s) * (2 * TILEB) + (uint32_t)(row2 * MST + 64 + 16 * h2) * 2; \
        const __nv_bfloat16* sH = aBase + 2 * K + 32 * (kt) + 16 * h2; \
        CPA(ah, sH); CPA(ah + 16, sH + 8); \
        asm volatile("cp.async.commit_group;\n"); }

#define LDGB(kt) { const float* p = bPtr + (size_t)(kt) * 32 * N; \
        _Pragma("unroll") \
        for (int i = 0; i < 16; i++) fb[i] = (!NGUARD || bValid) ? p[(size_t)i * N] : 0.f; }

#define CVTB(s) { __nv_bfloat16* Bs_ = smem + ATILE + (s) * (2 * ATILE); \
        uint32_t w_[16]; unsigned short ls_[16]; \
        _Pragma("unroll") \
        for (int i = 0; i < 16; i++) { \
            float x = fb[i]; \
            __nv_bfloat16 h = __float2bfloat16(x); \
            unsigned short hb = __bfloat16_as_ushort(h); \
            __nv_bfloat16 lo = __float2bfloat16(x - __bfloat162float(h)); \
            w_[i] = (uint32_t)hb | ((uint32_t)hb << 16); \
            ls_[i] = __bfloat16_as_ushort(lo); } \
        uint4* d0 = (uint4*)(Bs_ + bn * MST + bseg * 32); \
        const uint4* wv_ = (const uint4*)w_; \
        d0[0] = wv_[0]; d0[1] = wv_[1]; d0[2] = wv_[2]; d0[3] = wv_[3]; \
        uint32_t lw_[8]; \
        _Pragma("unroll") \
        for (int j = 0; j < 8; j++) lw_[j] = (uint32_t)ls_[2*j] | ((uint32_t)ls_[2*j+1] << 16); \
        uint4* d1 = (uint4*)(Bs_ + bn * MST + 64 + 16 * bseg); \
        d1[0] = ((const uint4*)lw_)[0]; d1[1] = ((const uint4*)lw_)[1]; }

#define MMAS(s) { uint32_t Ab = sbase + (s) * (2 * TILEB); \
        uint32_t Bb = sbase + TILEB + (s) * (2 * TILEB); \
        _Pragma("unroll") \
        for (int ks = 0; ks < 6; ks++) { \
            int kb = ks * 16; \
            uint32_t ra[4][4], rb[4][2]; \
            _Pragma("unroll") \
            for (int mf = 0; mf < 4; mf++) \
                ldsm4(ra[mf][0], ra[mf][1], ra[mf][2], ra[mf][3], \
                      Ab + 2u * (uint32_t)((wm * 64 + mf * 16) * MST + aoff + kb)); \
            _Pragma("unroll") \
            for (int p = 0; p < 2; p++) \
                ldsm4(rb[2*p][0], rb[2*p][1], rb[2*p+1][0], rb[2*p+1][1], \
                      Bb + 2u * (uint32_t)((wn * 32 + p * 16) * MST + boff + kb)); \
            _Pragma("unroll") \
            for (int mf = 0; mf < 4; mf++) \
                _Pragma("unroll") \
                for (int nf = 0; nf < 4; nf++) \
                    mma16816(acc[mf][nf], ra[mf][0], ra[mf][1], ra[mf][2], ra[mf][3], \
                             rb[nf][0], rb[nf][1]); } }

    int nt = K / 32;
    PREFA(0, 0);
    LDGB(0);
    CVTB(0);
    for (int kt = 0; kt < nt; kt++) {
        int s = kt & 1;
        if (kt + 1 < nt) {
            PREFA(s ^ 1, kt + 1);
            LDGB(kt + 1);
            asm volatile("cp.async.wait_group 1;\n" ::: "memory");
        } else {
            asm volatile("cp.async.wait_group 0;\n" ::: "memory");
        }
        __syncthreads();
        MMAS(s);
        if (kt + 1 < nt) CVTB(s ^ 1);
    }

    // ---- epilogue ----
    #pragma unroll
    for (int mf = 0; mf < 4; mf++) {
        int row0 = rowBlk + wm * 64 + mf * 16 + g;
        #pragma unroll
        for (int nf = 0; nf < 4; nf++) {
            int col = colBlk + wn * 32 + nf * 8 + tg * 2;
            float vals[4] = {acc[mf][nf].x, acc[mf][nf].y, acc[mf][nf].z, acc[mf][nf].w};
            #pragma unroll
            for (int h = 0; h < 2; h++) {
                int row = row0 + h * 8;
                float v0 = vals[h * 2], v1 = vals[h * 2 + 1];
                if (EPI == 0 || EPI == 1 || EPI == 2) {
                    v0 += bias[col]; v1 += bias[col + 1];
                }
                if (EPI == 2) {
                    v0 = 0.5f * v0 * (1.0f + erff(v0 * 0.7071067811865476f));
                    v1 = 0.5f * v1 * (1.0f + erff(v1 * 0.7071067811865476f));
                }
                if (EPI == 1) {
                    v0 += res[(size_t)row * N + col];
                    v1 += res[(size_t)row * N + col + 1];
                }
                if (EPI == 2) {
                    size_t rowb = (size_t)row * (size_t)(3 * N);
                    *(uint2*)(outP + rowb + 2 * col) = make_uint2(hilo32(v0), hilo32(v1));
                    *(uint32_t*)(outP + rowb + 2 * N + col) =
                        (uint32_t)bfhi(v0) | ((uint32_t)bfhi(v1) << 16);
                } else {
                    if (!NGUARD || col < N)     outF[(size_t)row * N + col] = v0;
                    if (!NGUARD || col + 1 < N) outF[(size_t)row * N + col + 1] = v1;
                }
            }
        }
    }
#undef PREFA
#undef LDGB
#undef CVTB
#undef MMAS
}

// =========================================================================
// Fused flash attention (packed g_yp epilogue)
// =========================================================================
#define FA_QST 200
#define FA_KST 200
#define FA_VST 136
#define FA_SMEM ((64*FA_QST + 64*FA_KST + 64*FA_VST)*2)

__global__ void __launch_bounds__(128, 2)
attn_fused_kernel() {
    extern __shared__ __nv_bfloat16 sm[];
    __nv_bfloat16* Qs = sm;
    __nv_bfloat16* Ks = sm + 64 * FA_QST;
    __nv_bfloat16* Vs = sm + 64 * (FA_QST + FA_KST);
    int tid = threadIdx.x, lane = tid & 31, warp = tid >> 5;
    int qt = blockIdx.x, bh = blockIdx.y;
    int b = bh >> 4, h = bh & 15;
    int g = lane >> 2, tg = lane & 3;
    int t8 = lane >> 3, r8 = lane & 7;
    uint32_t sb = (uint32_t)__cvta_generic_to_shared(sm);
    uint32_t Qb = sb;
    uint32_t Kb = sb + 64 * FA_QST * 2;
    uint32_t Vb = sb + 64 * (FA_QST + FA_KST) * 2;
    int aoff = ((t8 & 1) * 8 + r8) * FA_QST + (t8 >> 1) * 8;
    int koff = ((t8 >> 1) * 8 + r8) * FA_KST + (t8 & 1) * 8;
    int voff = ((t8 >> 1) * 8 + r8) * FA_VST + (t8 & 1) * 8;

    {
        int row = tid >> 1, seg = (tid & 1) * 32;
        const float* src = g_qkv + (size_t)(b * Tz + qt * 64 + row) * C3z + h * HDz + seg;
        uint32_t wbuf[32]; unsigned short hsb[32];
        #pragma unroll
        for (int i = 0; i < 8; i++) {
            float4 v = *(const float4*)(src + i * 4);
            float xs[4] = {v.x, v.y, v.z, v.w};
            #pragma unroll
            for (int e = 0; e < 4; e++) {
                float x = xs[e] * 0.125f;
                __nv_bfloat16 hb = __float2bfloat16(x);
                __nv_bfloat16 lb = __float2bfloat16(x - __bfloat162float(hb));
                int i4 = i * 4 + e;
                wbuf[i4] = (uint32_t)__bfloat16_as_ushort(hb) |
                           ((uint32_t)__bfloat16_as_ushort(lb) << 16);
                hsb[i4] = __bfloat16_as_ushort(hb);
            }
        }
        uint4* d0 = (uint4*)(Qs + row * FA_QST + 2 * seg);
        #pragma unroll
        for (int i = 0; i < 8; i++) d0[i] = ((const uint4*)wbuf)[i];
        uint32_t hw[16];
        #pragma unroll
        for (int j = 0; j < 16; j++)
            hw[j] = (uint32_t)hsb[2 * j] | ((uint32_t)hsb[2 * j + 1] << 16);
        uint4* d1 = (uint4*)(Qs + row * FA_QST + 128 + seg);
        #pragma unroll
        for (int i = 0; i < 4; i++) d1[i] = ((const uint4*)hw)[i];
    }

    float m0 = -1e30f, m1 = -1e30f, l0 = 0.f, l1 = 0.f;
    float4 O[8];
    #pragma unroll
    for (int i = 0; i < 8; i++) O[i] = make_float4(0.f, 0.f, 0.f, 0.f);

    for (int kt = 0; kt <= qt; kt++) {
        {
            int row = tid >> 1, seg = (tid & 1) * 32;
            const float* src = g_qkv + (size_t)(b * Tz + kt * 64 + row) * C3z + Cz + h * HDz + seg;
            uint32_t wbuf[32]; unsigned short lsb[32];
            #pragma unroll
            for (int i = 0; i < 8; i++) {
                float4 v = *(const float4*)(src + i * 4);
                float xs[4] = {v.x, v.y, v.z, v.w};
                #pragma unroll
                for (int e = 0; e < 4; e++) {
                    float x = xs[e];
                    __nv_bfloat16 hb = __float2bfloat16(x);
                    unsigned short hu = __bfloat16_as_ushort(hb);
                    __nv_bfloat16 lb = __float2bfloat16(x - __bfloat162float(hb));
                    int i4 = i * 4 + e;
                    wbuf[i4] = (uint32_t)hu | ((uint32_t)hu << 16);
                    lsb[i4] = __bfloat16_as_ushort(lb);
                }
            }
            uint4* d0 = (uint4*)(Ks + row * FA_KST + 2 * seg);
            #pragma unroll
            for (int i = 0; i < 8; i++) d0[i] = ((const uint4*)wbuf)[i];
            uint32_t lw[16];
            #pragma unroll
            for (int j = 0; j < 16; j++)
                lw[j] = (uint32_t)lsb[2 * j] | ((uint32_t)lsb[2 * j + 1] << 16);
            uint4* d1 = (uint4*)(Ks + row * FA_KST + 128 + seg);
            #pragma unroll
            for (int i = 0; i < 4; i++) d1[i] = ((const uint4*)lw)[i];
        }
        {
            int nd = (tid & 15) * 4;
            int k8 = (tid >> 4) * 8;
            unsigned short vh[4][8], vl[4][8];
            #pragma unroll
            for (int kk = 0; kk < 8; kk++) {
                const float* src = g_qkv + (size_t)(b * Tz + kt * 64 + k8 + kk) * C3z + 2 * Cz + h * HDz + nd;
                float4 v = *(const float4*)src;
                float xs[4] = {v.x, v.y, v.z, v.w};
                #pragma unroll
                for (int e = 0; e < 4; e++) {
                    float x = xs[e];
                    __nv_bfloat16 hb = __float2bfloat16(x);
                    __nv_bfloat16 lb = __float2bfloat16(x - __bfloat162float(hb));
                    vh[e][kk] = __bfloat16_as_ushort(hb);
                    vl[e][kk] = __bfloat16_as_ushort(lb);
                }
            }
            #pragma unroll
            for (int e = 0; e < 4; e++) {
                *(uint4*)(Vs + (nd + e) * FA_VST + k8)      = *(const uint4*)vh[e];
                *(uint4*)(Vs + (nd + e) * FA_VST + 64 + k8) = *(const uint4*)vl[e];
            }
        }
        __syncthreads();

        float4 S[8];
        #pragma unroll
        for (int i = 0; i < 8; i++) S[i] = make_float4(0.f, 0.f, 0.f, 0.f);
        #pragma unroll
        for (int ks = 0; ks < 12; ks++) {
            int kb = ks * 16;
            uint32_t ra0, ra1, ra2, ra3;
            ldsm4(ra0, ra1, ra2, ra3, Qb + 2u * (uint32_t)(warp * 16 * FA_QST + aoff + kb));
            #pragma unroll
            for (int pp = 0; pp < 4; pp++) {
                uint32_t b0, b1, b2, b3;
                ldsm4(b0, b1, b2, b3, Kb + 2u * (uint32_t)((pp * 16) * FA_KST + koff + kb));
                mma16816(S[2 * pp],     ra0, ra1, ra2, ra3, b0, b1);
                mma16816(S[2 * pp + 1], ra0, ra1, ra2, ra3, b2, b3);
            }
        }

        if (kt == qt) {
            int r0 = warp * 16 + g, r1 = r0 + 8;
            #pragma unroll
            for (int j = 0; j < 8; j++) {
                int c0 = j * 8 + 2 * tg, c1 = c0 + 1;
                if (c0 > r0) S[j].x = -1e30f;
                if (c1 > r0) S[j].y = -1e30f;
                if (c0 > r1) S[j].z = -1e30f;
                if (c1 > r1) S[j].w = -1e30f;
            }
        }

        float mx0 = -1e30f, mx1 = -1e30f;
        #pragma unroll
        for (int j = 0; j < 8; j++) {
            mx0 = fmaxf(mx0, fmaxf(S[j].x, S[j].y));
            mx1 = fmaxf(mx1, fmaxf(S[j].z, S[j].w));
        }
        mx0 = fmaxf(mx0, __shfl_xor_sync(0xffffffffu, mx0, 1));
        mx0 = fmaxf(mx0, __shfl_xor_sync(0xffffffffu, mx0, 2));
        mx1 = fmaxf(mx1, __shfl_xor_sync(0xffffffffu, mx1, 1));
        mx1 = fmaxf(mx1, __shfl_xor_sync(0xffffffffu, mx1, 2));
        float mn0 = fmaxf(m0, mx0), mn1 = fmaxf(m1, mx1);
        float al0 = __expf(m0 - mn0), al1 = __expf(m1 - mn1);
        m0 = mn0; m1 = mn1;
        float rs0 = 0.f, rs1 = 0.f;
        #pragma unroll
        for (int j = 0; j < 8; j++) {
            S[j].x = __expf(S[j].x - m0);
            S[j].y = __expf(S[j].y - m0);
            S[j].z = __expf(S[j].z - m1);
            S[j].w = __expf(S[j].w - m1);
            rs0 += S[j].x + S[j].y;
            rs1 += S[j].z + S[j].w;
        }
        rs0 += __shfl_xor_sync(0xffffffffu, rs0, 1);
        rs0 += __shfl_xor_sync(0xffffffffu, rs0, 2);
        rs1 += __shfl_xor_sync(0xffffffffu, rs1, 1);
        rs1 += __shfl_xor_sync(0xffffffffu, rs1, 2);
        l0 = l0 * al0 + rs0;
        l1 = l1 * al1 + rs1;
        #pragma unroll
        for (int j = 0; j < 8; j++) {
            O[j].x *= al0; O[j].y *= al0;
            O[j].z *= al1; O[j].w *= al1;
        }

        #pragma unroll
        for (int kc = 0; kc < 4; kc++) {
            float4 s0 = S[2 * kc], s1 = S[2 * kc + 1];
            float f0[8] = {s0.x, s0.y, s0.z, s0.w, s1.x, s1.y, s1.z, s1.w};
            unsigned short phs[8], pls[8];
            #pragma unroll
            for (int e = 0; e < 8; e++) {
                __nv_bfloat16 hb = __float2bfloat16(f0[e]);
                phs[e] = __bfloat16_as_ushort(hb);
                pls[e] = __bfloat16_as_ushort(__float2bfloat16(f0[e] - __bfloat162float(hb)));
            }
            uint32_t ph0 = (uint32_t)phs[0] | ((uint32_t)phs[1] << 16);
            uint32_t ph1 = (uint32_t)phs[2] | ((uint32_t)phs[3] << 16);
            uint32_t ph2 = (uint32_t)phs[4] | ((uint32_t)phs[5] << 16);
            uint32_t ph3 = (uint32_t)phs[6] | ((uint32_t)phs[7] << 16);
            uint32_t pl0 = (uint32_t)pls[0] | ((uint32_t)pls[1] << 16);
            uint32_t pl1 = (uint32_t)pls[2] | ((uint32_t)pls[3] << 16);
            uint32_t pl2 = (uint32_t)pls[4] | ((uint32_t)pls[5] << 16);
            uint32_t pl3 = (uint32_t)pls[6] | ((uint32_t)pls[7] << 16);

            uint32_t vh[8][2], vl[8][2];
            #pragma unroll
            for (int pp = 0; pp < 4; pp++) {
                ldsm4(vh[2*pp][0], vh[2*pp][1], vh[2*pp+1][0], vh[2*pp+1][1],
                      Vb + 2u * (uint32_t)((pp * 16) * FA_VST + voff + kc * 16));
                ldsm4(vl[2*pp][0], vl[2*pp][1], vl[2*pp+1][0], vl[2*pp+1][1],
                      Vb + 2u * (uint32_t)((pp * 16) * FA_VST + voff + 64 + kc * 16));
            }
            #pragma unroll
            for (int nf = 0; nf < 8; nf++) {
                mma16816(O[nf], ph0, ph1, ph2, ph3, vh[nf][0], vh[nf][1]);
                mma16816(O[nf], pl0, pl1, pl2, pl3, vh[nf][0], vh[nf][1]);
                mma16816(O[nf], ph0, ph1, ph2, ph3, vl[nf][0], vl[nf][1]);
            }
        }
        __syncthreads();
    }

    float i0 = 1.0f / l0, i1 = 1.0f / l1;
    int qrow = qt * 64 + warp * 16 + g;
    size_t rb0 = (size_t)(b * Tz + qrow) * C3z;
    size_t rb1 = (size_t)(b * Tz + qrow + 8) * C3z;
    #pragma unroll
    for (int nf = 0; nf < 8; nf++) {
        int colg = h * HDz + nf * 8 + 2 * tg;
        float vx = O[nf].x * i0, vy = O[nf].y * i0;
        float wx = O[nf].z * i1, wy = O[nf].w * i1;
        *(uint2*)(g_yp + rb0 + 2 * colg) = make_uint2(hilo32(vx), hilo32(vy));
        *(uint32_t*)(g_yp + rb0 + 2 * Cz + colg) = (uint32_t)bfhi(vx) | ((uint32_t)bfhi(vy) << 16);
        *(uint2*)(g_yp + rb1 + 2 * colg) = make_uint2(hilo32(wx), hilo32(wy));
        *(uint32_t*)(g_yp + rb1 + 2 * Cz + colg) = (uint32_t)bfhi(wx) | ((uint32_t)bfhi(wy) << 16);
    }
}

// ---------------- loss ----------------
__global__ void loss_row_kernel(const float* __restrict__ logits,
                                const int* __restrict__ targets) {
    int r = blockIdx.x;
    const float* row = logits + (size_t)r * Vz;
    int tid = threadIdx.x;
    float mx = -1e30f;
    for (int j = tid; j < Vz; j += 256) mx = fmaxf(mx, row[j]);
    mx = blockReduceMax(mx);
    float s = 0.f;
    for (int j = tid; j < Vz; j += 256) s += expf(row[j] - mx);
    s = blockReduceSum(s);
    if (tid == 0) {
        int t = targets[r];
        g_red[r] = -(row[t] - mx - logf(s));
    }
}

__global__ void loss_final_kernel(float* __restrict__ out, int out_size) {
    int tid = threadIdx.x;
    float s = 0.f;
    for (int j = tid; j < BTz; j += 256) s += g_red[j];
    s = blockReduceSum(s);
    if (tid == 0) {
        long long logits_elems = (long long)BTz * Vz;
        if ((long long)out_size > logits_elems)
            out[logits_elems] = s / (float)BTz;
    }
}

// ---------------- launch ----------------
extern "C" void kernel_launch(void* const* d_in, const int* in_sizes, int n_in,
                              void* d_out, int out_size) {
    const int*   idx     = (const int*)d_in[0];
    const int*   targets = (const int*)d_in[1];
    const float* tok_emb = (const float*)d_in[2];
    const float* pos_emb = (const float*)d_in[3];
    const float* ln1_w   = (const float*)d_in[4];
    const float* ln1_b   = (const float*)d_in[5];
    const float* ln2_w   = (const float*)d_in[6];
    const float* ln2_b   = (const float*)d_in[7];
    const float* Wq = (const float*)d_in[8];
    const float* bq = (const float*)d_in[9];
    const float* Wk = (const float*)d_in[10];
    const float* bk = (const float*)d_in[11];
    const float* Wv = (const float*)d_in[12];
    const float* bv = (const float*)d_in[13];
    const float* Wo = (const float*)d_in[14];
    const float* bo = (const float*)d_in[15];
    const float* W1 = (const float*)d_in[16];
    const float* b1 = (const float*)d_in[17];
    const float* W2 = (const float*)d_in[18];
    const float* b2 = (const float*)d_in[19];
    const float* lnf_w  = (const float*)d_in[20];
    const float* lnf_b  = (const float*)d_in[21];
    const float* head_w = (const float*)d_in[22];
    float* out = (float*)d_out;

    float *px, *pbp, *pwp, *pqkv;
    __nv_bfloat16 *php, *pffp, *pyp;
    cudaGetSymbolAddress((void**)&px,   g_x);
    cudaGetSymbolAddress((void**)&pbp,  g_bpack);
    cudaGetSymbolAddress((void**)&pwp,  g_wpack);
    cudaGetSymbolAddress((void**)&pqkv, g_qkv);
    cudaGetSymbolAddress((void**)&php,  g_hp);
    cudaGetSymbolAddress((void**)&pffp, g_ffp);
    cudaGetSymbolAddress((void**)&pyp,  g_yp);

    cudaFuncSetAttribute(gemm_pk_kernel<0, false>, cudaFuncAttributeMaxDynamicSharedMemorySize, GSMEM);
    cudaFuncSetAttribute(gemm_pk_kernel<1, false>, cudaFuncAttributeMaxDynamicSharedMemorySize, GSMEM);
    cudaFuncSetAttribute(gemm_pk_kernel<2, false>, cudaFuncAttributeMaxDynamicSharedMemorySize, GSMEM);
    cudaFuncSetAttribute(gemm_pk_kernel<3, true >, cudaFuncAttributeMaxDynamicSharedMemorySize, GSMEM);
    cudaFuncSetAttribute(attn_fused_kernel, cudaFuncAttributeMaxDynamicSharedMemorySize, FA_SMEM);

    embed_kernel<<<BTz, 256>>>(idx, tok_emb, pos_emb);

    const size_t CC  = (size_t)Cz * Cz;
    const size_t C14 = (size_t)Cz * C4z;
    dim3 gQKV(24, 16), gCC(8, 16), gC4(32, 16), gHead(393, 16);

    for (int l = 0; l < Lz; l++) {
        pack_w_kernel<<<dim3(Cz, 3), 256>>>(Wq + l * CC, Wk + l * CC, Wv + l * CC);
        pack_bias_kernel<<<3, 256>>>(bq + (size_t)l * Cz, bk + (size_t)l * Cz, bv + (size_t)l * Cz);
        ln_pack_kernel<<<BTz, 256>>>(px, ln1_w + (size_t)l * Cz, ln1_b + (size_t)l * Cz, php);
        gemm_pk_kernel<0, false><<<gQKV, 256, GSMEM>>>(php, pwp, pbp, nullptr, pqkv, nullptr, C3z, Cz);
        attn_fused_kernel<<<dim3(Tz / 64, Bz * Hz), 128, FA_SMEM>>>();
        gemm_pk_kernel<1, false><<<gCC, 256, GSMEM>>>(pyp, Wo + l * CC, bo + (size_t)l * Cz, px, px, nullptr, Cz, Cz);
        ln_pack_kernel<<<BTz, 256>>>(px, ln2_w + (size_t)l * Cz, ln2_b + (size_t)l * Cz, php);
        gemm_pk_kernel<2, false><<<gC4, 256, GSMEM>>>(php, W1 + l * C14, b1 + (size_t)l * C4z, nullptr, nullptr, pffp, C4z, Cz);
        gemm_pk_kernel<1, false><<<gCC, 256, GSMEM>>>(pffp, W2 + l * C14, b2 + (size_t)l * Cz, px, px, nullptr, Cz, C4z);
    }

    ln_pack_kernel<<<BTz, 256>>>(px, lnf_w, lnf_b, php);
    gemm_pk_kernel<3, true><<<gHead, 256, GSMEM>>>(php, head_w, nullptr, nullptr, out, nullptr, Vz, Cz);
    loss_row_kernel<<<BTz, 256>>>(out, targets);
    loss_final_kernel<<<1, 256>>>(out, out_size);
}

// round 10
// speedup vs baseline: 1.4064x; 1.1388x over previous
#include <cuda_runtime.h>
#include <cuda_bf16.h>
#include <math.h>
#include <stdint.h>

#define Bz 2
#define Tz 1024
#define Cz 1024
#define Hz 16
#define HDz 64
#define Lz 12
#define Vz 50257
#define BTz (Bz*Tz)
#define C4z (4*Cz)
#define C3z (3*Cz)

// ---------------- scratch (device globals; no allocation) ----------------
__device__ float g_x[BTz*Cz];                         // residual (fp32)
__device__ float g_qkv[(size_t)BTz*C3z];              // QKV output (fp32, attn input)
__device__ float g_red[BTz];
__device__ float g_bpack[C3z];
__device__ float g_wpack[(size_t)Cz*C3z];             // QKV weights concat (fp32)
__device__ __nv_bfloat16 g_hp [(size_t)BTz*2*Cz];     // LN output [hi K | lo K]
__device__ __nv_bfloat16 g_yp [(size_t)BTz*2*Cz];     // attn output [hi | lo]
__device__ __nv_bfloat16 g_ffp[(size_t)BTz*2*C4z];    // MLP hidden [hi | lo]

// ---------------- helpers ----------------
__device__ __forceinline__ unsigned short bfhi(float x) {
    return __bfloat16_as_ushort(__float2bfloat16(x));
}
__device__ __forceinline__ unsigned short bflo(float x) {
    __nv_bfloat16 h = __float2bfloat16(x);
    return __bfloat16_as_ushort(__float2bfloat16(x - __bfloat162float(h)));
}

__device__ __forceinline__ float blockReduceSum(float v) {
    __shared__ float sh[33];
    int lane = threadIdx.x & 31, w = threadIdx.x >> 5;
    #pragma unroll
    for (int o = 16; o; o >>= 1) v += __shfl_down_sync(0xffffffffu, v, o);
    __syncthreads();
    if (lane == 0) sh[w] = v;
    __syncthreads();
    if (threadIdx.x == 0) {
        float s = 0.f;
        int nw = blockDim.x >> 5;
        for (int i = 0; i < nw; i++) s += sh[i];
        sh[32] = s;
    }
    __syncthreads();
    return sh[32];
}

__device__ __forceinline__ float blockReduceMax(float v) {
    __shared__ float sh[33];
    int lane = threadIdx.x & 31, w = threadIdx.x >> 5;
    #pragma unroll
    for (int o = 16; o; o >>= 1) v = fmaxf(v, __shfl_down_sync(0xffffffffu, v, o));
    __syncthreads();
    if (lane == 0) sh[w] = v;
    __syncthreads();
    if (threadIdx.x == 0) {
        float s = -1e30f;
        int nw = blockDim.x >> 5;
        for (int i = 0; i < nw; i++) s = fmaxf(s, sh[i]);
        sh[32] = s;
    }
    __syncthreads();
    return sh[32];
}

// ---------------- embedding ----------------
__global__ void embed_kernel(const int* __restrict__ idx,
                             const float* __restrict__ tok,
                             const float* __restrict__ pos) {
    int r = blockIdx.x;
    int c = threadIdx.x * 4;
    int tokid = idx[r];
    float4 te = *(const float4*)(tok + (size_t)tokid * Cz + c);
    float4 pe = *(const float4*)(pos + (size_t)(r % Tz) * Cz + c);
    float4 o;
    o.x = te.x + pe.x; o.y = te.y + pe.y; o.z = te.z + pe.z; o.w = te.w + pe.w;
    *(float4*)(g_x + (size_t)r * Cz + c) = o;
}

// ---------------- layernorm -> packed A rows [hi C | lo C] ----------------
__global__ void ln_pack_kernel(const float* __restrict__ x,
                               const float* __restrict__ w,
                               const float* __restrict__ b,
                               __nv_bfloat16* __restrict__ outp) {
    int r = blockIdx.x;
    const float* xr = x + (size_t)r * Cz;
    float v[4];
    #pragma unroll
    for (int k = 0; k < 4; k++) v[k] = xr[threadIdx.x + k * 256];
    float s = v[0] + v[1] + v[2] + v[3];
    s = blockReduceSum(s);
    float mu = s * (1.0f / Cz);
    float sq = 0.f;
    #pragma unroll
    for (int k = 0; k < 4; k++) { float d = v[k] - mu; sq += d * d; }
    sq = blockReduceSum(sq);
    float rstd = rsqrtf(sq * (1.0f / Cz) + 1e-5f);
    __nv_bfloat16* orow = outp + (size_t)r * 2 * Cz;
    #pragma unroll
    for (int k = 0; k < 4; k++) {
        int c = threadIdx.x + k * 256;
        float xv = (v[k] - mu) * rstd * w[c] + b[c];
        __nv_bfloat16 hb = __float2bfloat16(xv);
        orow[c] = hb;
        orow[Cz + c] = __float2bfloat16(xv - __bfloat162float(hb));
    }
}

// ---------------- QKV weight/bias concat (fp32) ----------------
__global__ void pack_w_kernel(const float* __restrict__ Wq,
                              const float* __restrict__ Wk,
                              const float* __restrict__ Wv) {
    int which = blockIdx.y;
    const float* src = (which == 0) ? Wq : (which == 1) ? Wk : Wv;
    int k = blockIdx.x;
    int c = threadIdx.x * 4;
    float4 v = *(const float4*)(src + (size_t)k * Cz + c);
    *(float4*)(g_wpack + (size_t)k * C3z + which * Cz + c) = v;
}

__global__ void pack_bias_kernel(const float* __restrict__ bq,
                                 const float* __restrict__ bk,
                                 const float* __restrict__ bv) {
    int which = blockIdx.x;
    const float* src = (which == 0) ? bq : (which == 1) ? bk : bv;
    int c = threadIdx.x * 4;
    float4 v = *(const float4*)(src + c);
    *(float4*)(g_bpack + which * Cz + c) = v;
}

// ---------------- mma / ldmatrix primitives ----------------
__device__ __forceinline__ void mma16816(float4& c, uint32_t a0, uint32_t a1,
                                         uint32_t a2, uint32_t a3,
                                         uint32_t b0, uint32_t b1) {
    asm volatile(
        "mma.sync.aligned.m16n8k16.row.col.f32.bf16.bf16.f32 "
        "{%0,%1,%2,%3}, {%4,%5,%6,%7}, {%8,%9}, {%0,%1,%2,%3};"
        : "+f"(c.x), "+f"(c.y), "+f"(c.z), "+f"(c.w)
        : "r"(a0), "r"(a1), "r"(a2), "r"(a3), "r"(b0), "r"(b1));
}

__device__ __forceinline__ void ldsm4(uint32_t& r0, uint32_t& r1,
                                      uint32_t& r2, uint32_t& r3, uint32_t addr) {
    asm volatile("ldmatrix.sync.aligned.m8n8.x4.shared.b16 {%0,%1,%2,%3}, [%4];"
        : "=r"(r0), "=r"(r1), "=r"(r2), "=r"(r3) : "r"(addr));
}

// =========================================================================
// GEMM, shared-segment hi/lo: A SMEM [128 x (ah32|al32)], B SMEM [128n x (bh32|bl32)]
// 3 MMA passes per kstep with fragment reuse. Stride 72 bf16 (9x16B, odd).
// EPI: 0=bias->f32, 1=bias+res->f32, 2=bias+gelu->packed[hi|lo], 3=plain->f32
// =========================================================================
#define AST 72
#define ATILEB (128*AST*2)        // 18432 B per A (or B) tile
#define BUFSZ (2*ATILEB)          // A+B per stage
#define GSMEM (2*BUFSZ)           // double buffered = 73728 B

#define CPA(dst, src) asm volatile("cp.async.cg.shared.global [%0], [%1], 16;\n" :: "r"(dst), "l"(src))

template<int EPI, bool NGUARD>
__global__ void __launch_bounds__(256, 1)
gemm_pk_kernel(const __nv_bfloat16* __restrict__ Apack,
               const float* __restrict__ Bm,
               const float* __restrict__ bias, const float* __restrict__ res,
               float* __restrict__ outF, __nv_bfloat16* __restrict__ outP,
               int N, int K) {
    extern __shared__ __nv_bfloat16 smem[];
    int tid = threadIdx.x, lane = tid & 31, warp = tid >> 5;
    int wm = warp & 1, wn = warp >> 1;
    int g = lane >> 2, tg = lane & 3;
    int rowBlk = blockIdx.y * 128, colBlk = blockIdx.x * 128;
    int row2 = tid >> 1, h2 = tid & 1;          // A staging: 128 rows x {hi,lo}
    int bn = tid & 127, kseg = tid >> 7;        // B staging: 128 cols x 2 k-halves
    int t8 = lane >> 3, r8 = lane & 7;
    int aoff = ((t8 & 1) * 8 + r8) * AST + (t8 >> 1) * 8;
    int boff = ((t8 >> 1) * 8 + r8) * AST + (t8 & 1) * 8;
    uint32_t sbase = (uint32_t)__cvta_generic_to_shared(smem);

    const __nv_bfloat16* aRow = Apack + (size_t)(rowBlk + row2) * (2 * K) + (size_t)h2 * K;
    int nb = colBlk + bn;
    bool bValid = (!NGUARD) || (nb < N);
    const float* bPtr = Bm + (bValid ? nb : 0);

    float fb[16];
    float4 acc[4][4];
    #pragma unroll
    for (int i = 0; i < 4; i++)
        #pragma unroll
        for (int j = 0; j < 4; j++) acc[i][j] = make_float4(0.f, 0.f, 0.f, 0.f);

#define PREFA(s, kt) { \
        uint32_t ad_ = sbase + (s) * BUFSZ + (uint32_t)(row2 * AST + h2 * 32) * 2; \
        const __nv_bfloat16* sA_ = aRow + (kt) * 32; \
        CPA(ad_, sA_); CPA(ad_ + 16, sA_ + 8); CPA(ad_ + 32, sA_ + 16); CPA(ad_ + 48, sA_ + 24); \
        asm volatile("cp.async.commit_group;\n"); }

#define LDGB(kt) { const float* p = bPtr + (size_t)((kt) * 32 + kseg * 16) * N; \
        _Pragma("unroll") \
        for (int i = 0; i < 16; i++) fb[i] = (!NGUARD || bValid) ? p[(size_t)i * N] : 0.f; }

#define CVTB(s) { \
        unsigned short hs_[16], ls_[16]; \
        _Pragma("unroll") \
        for (int i = 0; i < 16; i++) { \
            float x = fb[i]; \
            __nv_bfloat16 h = __float2bfloat16(x); \
            hs_[i] = __bfloat16_as_ushort(h); \
            ls_[i] = __bfloat16_as_ushort(__float2bfloat16(x - __bfloat162float(h))); } \
        __nv_bfloat16* Bs_ = smem + ((s) * BUFSZ + ATILEB) / 2 + bn * AST; \
        uint4* dh = (uint4*)(Bs_ + kseg * 16); \
        dh[0] = ((const uint4*)hs_)[0]; dh[1] = ((const uint4*)hs_)[1]; \
        uint4* dl = (uint4*)(Bs_ + 32 + kseg * 16); \
        dl[0] = ((const uint4*)ls_)[0]; dl[1] = ((const uint4*)ls_)[1]; }

#define MMAS(s) { uint32_t Ab = sbase + (s) * BUFSZ; \
        uint32_t Bb = Ab + ATILEB; \
        _Pragma("unroll") \
        for (int kh = 0; kh < 2; kh++) { \
            int kbh = kh * 16; \
            uint32_t ah[4][4], al[4][4], rbh[4][2], rbl[4][2]; \
            _Pragma("unroll") \
            for (int mf = 0; mf < 4; mf++) { \
                ldsm4(ah[mf][0], ah[mf][1], ah[mf][2], ah[mf][3], \
                      Ab + 2u * (uint32_t)((wm * 64 + mf * 16) * AST + aoff + kbh)); \
                ldsm4(al[mf][0], al[mf][1], al[mf][2], al[mf][3], \
                      Ab + 2u * (uint32_t)((wm * 64 + mf * 16) * AST + aoff + 32 + kbh)); } \
            _Pragma("unroll") \
            for (int p = 0; p < 2; p++) { \
                ldsm4(rbh[2*p][0], rbh[2*p][1], rbh[2*p+1][0], rbh[2*p+1][1], \
                      Bb + 2u * (uint32_t)((wn * 32 + p * 16) * AST + boff + kbh)); \
                ldsm4(rbl[2*p][0], rbl[2*p][1], rbl[2*p+1][0], rbl[2*p+1][1], \
                      Bb + 2u * (uint32_t)((wn * 32 + p * 16) * AST + boff + 32 + kbh)); } \
            _Pragma("unroll") \
            for (int mf = 0; mf < 4; mf++) \
                _Pragma("unroll") \
                for (int nf = 0; nf < 4; nf++) { \
                    mma16816(acc[mf][nf], ah[mf][0], ah[mf][1], ah[mf][2], ah[mf][3], \
                             rbh[nf][0], rbh[nf][1]); \
                    mma16816(acc[mf][nf], al[mf][0], al[mf][1], al[mf][2], al[mf][3], \
                             rbh[nf][0], rbh[nf][1]); \
                    mma16816(acc[mf][nf], ah[mf][0], ah[mf][1], ah[mf][2], ah[mf][3], \
                             rbl[nf][0], rbl[nf][1]); } } }

    int nt = K / 32;
    PREFA(0, 0);
    LDGB(0);
    CVTB(0);
    for (int kt = 0; kt < nt; kt++) {
        int s = kt & 1;
        if (kt + 1 < nt) {
            PREFA(s ^ 1, kt + 1);
            LDGB(kt + 1);
            asm volatile("cp.async.wait_group 1;\n" ::: "memory");
        } else {
            asm volatile("cp.async.wait_group 0;\n" ::: "memory");
        }
        __syncthreads();
        MMAS(s);
        if (kt + 1 < nt) CVTB(s ^ 1);
    }

    // ---- epilogue ----
    #pragma unroll
    for (int mf = 0; mf < 4; mf++) {
        int row0 = rowBlk + wm * 64 + mf * 16 + g;
        #pragma unroll
        for (int nf = 0; nf < 4; nf++) {
            int col = colBlk + wn * 32 + nf * 8 + tg * 2;
            float vals[4] = {acc[mf][nf].x, acc[mf][nf].y, acc[mf][nf].z, acc[mf][nf].w};
            #pragma unroll
            for (int h = 0; h < 2; h++) {
                int row = row0 + h * 8;
                float v0 = vals[h * 2], v1 = vals[h * 2 + 1];
                if (EPI == 0 || EPI == 1 || EPI == 2) {
                    v0 += bias[col]; v1 += bias[col + 1];
                }
                if (EPI == 2) {
                    v0 = 0.5f * v0 * (1.0f + erff(v0 * 0.7071067811865476f));
                    v1 = 0.5f * v1 * (1.0f + erff(v1 * 0.7071067811865476f));
                }
                if (EPI == 1) {
                    v0 += res[(size_t)row * N + col];
                    v1 += res[(size_t)row * N + col + 1];
                }
                if (EPI == 2) {
                    size_t rowb = (size_t)row * (size_t)(2 * N);
                    *(uint32_t*)(outP + rowb + col) =
                        (uint32_t)bfhi(v0) | ((uint32_t)bfhi(v1) << 16);
                    *(uint32_t*)(outP + rowb + N + col) =
                        (uint32_t)bflo(v0) | ((uint32_t)bflo(v1) << 16);
                } else {
                    if (!NGUARD || col < N)     outF[(size_t)row * N + col] = v0;
                    if (!NGUARD || col + 1 < N) outF[(size_t)row * N + col + 1] = v1;
                }
            }
        }
    }
#undef PREFA
#undef LDGB
#undef CVTB
#undef MMAS
}

// =========================================================================
// Fused flash attention (epilogue writes g_yp [hi C | lo C])
// =========================================================================
#define FA_QST 200
#define FA_KST 200
#define FA_VST 136
#define FA_SMEM ((64*FA_QST + 64*FA_KST + 64*FA_VST)*2)

__global__ void __launch_bounds__(128, 2)
attn_fused_kernel() {
    extern __shared__ __nv_bfloat16 sm[];
    __nv_bfloat16* Qs = sm;
    __nv_bfloat16* Ks = sm + 64 * FA_QST;
    __nv_bfloat16* Vs = sm + 64 * (FA_QST + FA_KST);
    int tid = threadIdx.x, lane = tid & 31, warp = tid >> 5;
    int qt = blockIdx.x, bh = blockIdx.y;
    int b = bh >> 4, h = bh & 15;
    int g = lane >> 2, tg = lane & 3;
    int t8 = lane >> 3, r8 = lane & 7;
    uint32_t sbb = (uint32_t)__cvta_generic_to_shared(sm);
    uint32_t Qb = sbb;
    uint32_t Kb = sbb + 64 * FA_QST * 2;
    uint32_t Vb = sbb + 64 * (FA_QST + FA_KST) * 2;
    int aoff = ((t8 & 1) * 8 + r8) * FA_QST + (t8 >> 1) * 8;
    int koff = ((t8 >> 1) * 8 + r8) * FA_KST + (t8 & 1) * 8;
    int voff = ((t8 >> 1) * 8 + r8) * FA_VST + (t8 & 1) * 8;

    {
        int row = tid >> 1, seg = (tid & 1) * 32;
        const float* src = g_qkv + (size_t)(b * Tz + qt * 64 + row) * C3z + h * HDz + seg;
        uint32_t wbuf[32]; unsigned short hsb[32];
        #pragma unroll
        for (int i = 0; i < 8; i++) {
            float4 v = *(const float4*)(src + i * 4);
            float xs[4] = {v.x, v.y, v.z, v.w};
            #pragma unroll
            for (int e = 0; e < 4; e++) {
                float x = xs[e] * 0.125f;
                __nv_bfloat16 hb = __float2bfloat16(x);
                __nv_bfloat16 lb = __float2bfloat16(x - __bfloat162float(hb));
                int i4 = i * 4 + e;
                wbuf[i4] = (uint32_t)__bfloat16_as_ushort(hb) |
                           ((uint32_t)__bfloat16_as_ushort(lb) << 16);
                hsb[i4] = __bfloat16_as_ushort(hb);
            }
        }
        uint4* d0 = (uint4*)(Qs + row * FA_QST + 2 * seg);
        #pragma unroll
        for (int i = 0; i < 8; i++) d0[i] = ((const uint4*)wbuf)[i];
        uint32_t hw[16];
        #pragma unroll
        for (int j = 0; j < 16; j++)
            hw[j] = (uint32_t)hsb[2 * j] | ((uint32_t)hsb[2 * j + 1] << 16);
        uint4* d1 = (uint4*)(Qs + row * FA_QST + 128 + seg);
        #pragma unroll
        for (int i = 0; i < 4; i++) d1[i] = ((const uint4*)hw)[i];
    }

    float m0 = -1e30f, m1 = -1e30f, l0 = 0.f, l1 = 0.f;
    float4 O[8];
    #pragma unroll
    for (int i = 0; i < 8; i++) O[i] = make_float4(0.f, 0.f, 0.f, 0.f);

    for (int kt = 0; kt <= qt; kt++) {
        {
            int row = tid >> 1, seg = (tid & 1) * 32;
            const float* src = g_qkv + (size_t)(b * Tz + kt * 64 + row) * C3z + Cz + h * HDz + seg;
            uint32_t wbuf[32]; unsigned short lsb[32];
            #pragma unroll
            for (int i = 0; i < 8; i++) {
                float4 v = *(const float4*)(src + i * 4);
                float xs[4] = {v.x, v.y, v.z, v.w};
                #pragma unroll
                for (int e = 0; e < 4; e++) {
                    float x = xs[e];
                    __nv_bfloat16 hb = __float2bfloat16(x);
                    unsigned short hu = __bfloat16_as_ushort(hb);
                    __nv_bfloat16 lb = __float2bfloat16(x - __bfloat162float(hb));
                    int i4 = i * 4 + e;
                    wbuf[i4] = (uint32_t)hu | ((uint32_t)hu << 16);
                    lsb[i4] = __bfloat16_as_ushort(lb);
                }
            }
            uint4* d0 = (uint4*)(Ks + row * FA_KST + 2 * seg);
            #pragma unroll
            for (int i = 0; i < 8; i++) d0[i] = ((const uint4*)wbuf)[i];
            uint32_t lw[16];
            #pragma unroll
            for (int j = 0; j < 16; j++)
                lw[j] = (uint32_t)lsb[2 * j] | ((uint32_t)lsb[2 * j + 1] << 16);
            uint4* d1 = (uint4*)(Ks + row * FA_KST + 128 + seg);
            #pragma unroll
            for (int i = 0; i < 4; i++) d1[i] = ((const uint4*)lw)[i];
        }
        {
            int nd = (tid & 15) * 4;
            int k8 = (tid >> 4) * 8;
            unsigned short vh[4][8], vl[4][8];
            #pragma unroll
            for (int kk = 0; kk < 8; kk++) {
                const float* src = g_qkv + (size_t)(b * Tz + kt * 64 + k8 + kk) * C3z + 2 * Cz + h * HDz + nd;
                float4 v = *(const float4*)src;
                float xs[4] = {v.x, v.y, v.z, v.w};
                #pragma unroll
                for (int e = 0; e < 4; e++) {
                    float x = xs[e];
                    __nv_bfloat16 hb = __float2bfloat16(x);
                    __nv_bfloat16 lb = __float2bfloat16(x - __bfloat162float(hb));
                    vh[e][kk] = __bfloat16_as_ushort(hb);
                    vl[e][kk] = __bfloat16_as_ushort(lb);
                }
            }
            #pragma unroll
            for (int e = 0; e < 4; e++) {
                *(uint4*)(Vs + (nd + e) * FA_VST + k8)      = *(const uint4*)vh[e];
                *(uint4*)(Vs + (nd + e) * FA_VST + 64 + k8) = *(const uint4*)vl[e];
            }
        }
        __syncthreads();

        float4 S[8];
        #pragma unroll
        for (int i = 0; i < 8; i++) S[i] = make_float4(0.f, 0.f, 0.f, 0.f);
        #pragma unroll
        for (int ks = 0; ks < 12; ks++) {
            int kb = ks * 16;
            uint32_t ra0, ra1, ra2, ra3;
            ldsm4(ra0, ra1, ra2, ra3, Qb + 2u * (uint32_t)(warp * 16 * FA_QST + aoff + kb));
            #pragma unroll
            for (int pp = 0; pp < 4; pp++) {
                uint32_t b0, b1, b2, b3;
                ldsm4(b0, b1, b2, b3, Kb + 2u * (uint32_t)((pp * 16) * FA_KST + koff + kb));
                mma16816(S[2 * pp],     ra0, ra1, ra2, ra3, b0, b1);
                mma16816(S[2 * pp + 1], ra0, ra1, ra2, ra3, b2, b3);
            }
        }

        if (kt == qt) {
            int r0 = warp * 16 + g, r1 = r0 + 8;
            #pragma unroll
            for (int j = 0; j < 8; j++) {
                int c0 = j * 8 + 2 * tg, c1 = c0 + 1;
                if (c0 > r0) S[j].x = -1e30f;
                if (c1 > r0) S[j].y = -1e30f;
                if (c0 > r1) S[j].z = -1e30f;
                if (c1 > r1) S[j].w = -1e30f;
            }
        }

        float mx0 = -1e30f, mx1 = -1e30f;
        #pragma unroll
        for (int j = 0; j < 8; j++) {
            mx0 = fmaxf(mx0, fmaxf(S[j].x, S[j].y));
            mx1 = fmaxf(mx1, fmaxf(S[j].z, S[j].w));
        }
        mx0 = fmaxf(mx0, __shfl_xor_sync(0xffffffffu, mx0, 1));
        mx0 = fmaxf(mx0, __shfl_xor_sync(0xffffffffu, mx0, 2));
        mx1 = fmaxf(mx1, __shfl_xor_sync(0xffffffffu, mx1, 1));
        mx1 = fmaxf(mx1, __shfl_xor_sync(0xffffffffu, mx1, 2));
        float mn0 = fmaxf(m0, mx0), mn1 = fmaxf(m1, mx1);
        float al0 = __expf(m0 - mn0), al1 = __expf(m1 - mn1);
        m0 = mn0; m1 = mn1;
        float rs0 = 0.f, rs1 = 0.f;
        #pragma unroll
        for (int j = 0; j < 8; j++) {
            S[j].x = __expf(S[j].x - m0);
            S[j].y = __expf(S[j].y - m0);
            S[j].z = __expf(S[j].z - m1);
            S[j].w = __expf(S[j].w - m1);
            rs0 += S[j].x + S[j].y;
            rs1 += S[j].z + S[j].w;
        }
        rs0 += __shfl_xor_sync(0xffffffffu, rs0, 1);
        rs0 += __shfl_xor_sync(0xffffffffu, rs0, 2);
        rs1 += __shfl_xor_sync(0xffffffffu, rs1, 1);
        rs1 += __shfl_xor_sync(0xffffffffu, rs1, 2);
        l0 = l0 * al0 + rs0;
        l1 = l1 * al1 + rs1;
        #pragma unroll
        for (int j = 0; j < 8; j++) {
            O[j].x *= al0; O[j].y *= al0;
            O[j].z *= al1; O[j].w *= al1;
        }

        #pragma unroll
        for (int kc = 0; kc < 4; kc++) {
            float4 s0 = S[2 * kc], s1 = S[2 * kc + 1];
            float f0[8] = {s0.x, s0.y, s0.z, s0.w, s1.x, s1.y, s1.z, s1.w};
            unsigned short phs[8], pls[8];
            #pragma unroll
            for (int e = 0; e < 8; e++) {
                __nv_bfloat16 hb = __float2bfloat16(f0[e]);
                phs[e] = __bfloat16_as_ushort(hb);
                pls[e] = __bfloat16_as_ushort(__float2bfloat16(f0[e] - __bfloat162float(hb)));
            }
            uint32_t ph0 = (uint32_t)phs[0] | ((uint32_t)phs[1] << 16);
            uint32_t ph1 = (uint32_t)phs[2] | ((uint32_t)phs[3] << 16);
            uint32_t ph2 = (uint32_t)phs[4] | ((uint32_t)phs[5] << 16);
            uint32_t ph3 = (uint32_t)phs[6] | ((uint32_t)phs[7] << 16);
            uint32_t pl0 = (uint32_t)pls[0] | ((uint32_t)pls[1] << 16);
            uint32_t pl1 = (uint32_t)pls[2] | ((uint32_t)pls[3] << 16);
            uint32_t pl2 = (uint32_t)pls[4] | ((uint32_t)pls[5] << 16);
            uint32_t pl3 = (uint32_t)pls[6] | ((uint32_t)pls[7] << 16);

            uint32_t vh[8][2], vl[8][2];
            #pragma unroll
            for (int pp = 0; pp < 4; pp++) {
                ldsm4(vh[2*pp][0], vh[2*pp][1], vh[2*pp+1][0], vh[2*pp+1][1],
                      Vb + 2u * (uint32_t)((pp * 16) * FA_VST + voff + kc * 16));
                ldsm4(vl[2*pp][0], vl[2*pp][1], vl[2*pp+1][0], vl[2*pp+1][1],
                      Vb + 2u * (uint32_t)((pp * 16) * FA_VST + voff + 64 + kc * 16));
            }
            #pragma unroll
            for (int nf = 0; nf < 8; nf++) {
                mma16816(O[nf], ph0, ph1, ph2, ph3, vh[nf][0], vh[nf][1]);
                mma16816(O[nf], pl0, pl1, pl2, pl3, vh[nf][0], vh[nf][1]);
                mma16816(O[nf], ph0, ph1, ph2, ph3, vl[nf][0], vl[nf][1]);
            }
        }
        __syncthreads();
    }

    float i0 = 1.0f / l0, i1 = 1.0f / l1;
    int qrow = qt * 64 + warp * 16 + g;
    size_t rb0 = (size_t)(b * Tz + qrow) * (2 * Cz);
    size_t rb1 = (size_t)(b * Tz + qrow + 8) * (2 * Cz);
    #pragma unroll
    for (int nf = 0; nf < 8; nf++) {
        int colg = h * HDz + nf * 8 + 2 * tg;
        float vx = O[nf].x * i0, vy = O[nf].y * i0;
        float wx = O[nf].z * i1, wy = O[nf].w * i1;
        *(uint32_t*)(g_yp + rb0 + colg)      = (uint32_t)bfhi(vx) | ((uint32_t)bfhi(vy) << 16);
        *(uint32_t*)(g_yp + rb0 + Cz + colg) = (uint32_t)bflo(vx) | ((uint32_t)bflo(vy) << 16);
        *(uint32_t*)(g_yp + rb1 + colg)      = (uint32_t)bfhi(wx) | ((uint32_t)bfhi(wy) << 16);
        *(uint32_t*)(g_yp + rb1 + Cz + colg) = (uint32_t)bflo(wx) | ((uint32_t)bflo(wy) << 16);
    }
}

// ---------------- loss ----------------
__global__ void loss_row_kernel(const float* __restrict__ logits,
                                const int* __restrict__ targets) {
    int r = blockIdx.x;
    const float* row = logits + (size_t)r * Vz;
    int tid = threadIdx.x;
    float mx = -1e30f;
    for (int j = tid; j < Vz; j += 256) mx = fmaxf(mx, row[j]);
    mx = blockReduceMax(mx);
    float s = 0.f;
    for (int j = tid; j < Vz; j += 256) s += expf(row[j] - mx);
    s = blockReduceSum(s);
    if (tid == 0) {
        int t = targets[r];
        g_red[r] = -(row[t] - mx - logf(s));
    }
}

__global__ void loss_final_kernel(float* __restrict__ out, int out_size) {
    int tid = threadIdx.x;
    float s = 0.f;
    for (int j = tid; j < BTz; j += 256) s += g_red[j];
    s = blockReduceSum(s);
    if (tid == 0) {
        long long logits_elems = (long long)BTz * Vz;
        if ((long long)out_size > logits_elems)
            out[logits_elems] = s / (float)BTz;
    }
}

// ---------------- launch ----------------
extern "C" void kernel_launch(void* const* d_in, const int* in_sizes, int n_in,
                              void* d_out, int out_size) {
    const int*   idx     = (const int*)d_in[0];
    const int*   targets = (const int*)d_in[1];
    const float* tok_emb = (const float*)d_in[2];
    const float* pos_emb = (const float*)d_in[3];
    const float* ln1_w   = (const float*)d_in[4];
    const float* ln1_b   = (const float*)d_in[5];
    const float* ln2_w   = (const float*)d_in[6];
    const float* ln2_b   = (const float*)d_in[7];
    const float* Wq = (const float*)d_in[8];
    const float* bq = (const float*)d_in[9];
    const float* Wk = (const float*)d_in[10];
    const float* bk = (const float*)d_in[11];
    const float* Wv = (const float*)d_in[12];
    const float* bv = (const float*)d_in[13];
    const float* Wo = (const float*)d_in[14];
    const float* bo = (const float*)d_in[15];
    const float* W1 = (const float*)d_in[16];
    const float* b1 = (const float*)d_in[17];
    const float* W2 = (const float*)d_in[18];
    const float* b2 = (const float*)d_in[19];
    const float* lnf_w  = (const float*)d_in[20];
    const float* lnf_b  = (const float*)d_in[21];
    const float* head_w = (const float*)d_in[22];
    float* out = (float*)d_out;

    float *px, *pbp, *pwp, *pqkv;
    __nv_bfloat16 *php, *pffp, *pyp;
    cudaGetSymbolAddress((void**)&px,   g_x);
    cudaGetSymbolAddress((void**)&pbp,  g_bpack);
    cudaGetSymbolAddress((void**)&pwp,  g_wpack);
    cudaGetSymbolAddress((void**)&pqkv, g_qkv);
    cudaGetSymbolAddress((void**)&php,  g_hp);
    cudaGetSymbolAddress((void**)&pffp, g_ffp);
    cudaGetSymbolAddress((void**)&pyp,  g_yp);

    cudaFuncSetAttribute(gemm_pk_kernel<0, false>, cudaFuncAttributeMaxDynamicSharedMemorySize, GSMEM);
    cudaFuncSetAttribute(gemm_pk_kernel<1, false>, cudaFuncAttributeMaxDynamicSharedMemorySize, GSMEM);
    cudaFuncSetAttribute(gemm_pk_kernel<2, false>, cudaFuncAttributeMaxDynamicSharedMemorySize, GSMEM);
    cudaFuncSetAttribute(gemm_pk_kernel<3, true >, cudaFuncAttributeMaxDynamicSharedMemorySize, GSMEM);
    cudaFuncSetAttribute(attn_fused_kernel, cudaFuncAttributeMaxDynamicSharedMemorySize, FA_SMEM);

    embed_kernel<<<BTz, 256>>>(idx, tok_emb, pos_emb);

    const size_t CC  = (size_t)Cz * Cz;
    const size_t C14 = (size_t)Cz * C4z;
    dim3 gQKV(24, 16), gCC(8, 16), gC4(32, 16), gHead(393, 16);

    for (int l = 0; l < Lz; l++) {
        pack_w_kernel<<<dim3(Cz, 3), 256>>>(Wq + l * CC, Wk + l * CC, Wv + l * CC);
        pack_bias_kernel<<<3, 256>>>(bq + (size_t)l * Cz, bk + (size_t)l * Cz, bv + (size_t)l * Cz);
        ln_pack_kernel<<<BTz, 256>>>(px, ln1_w + (size_t)l * Cz, ln1_b + (size_t)l * Cz, php);
        gemm_pk_kernel<0, false><<<gQKV, 256, GSMEM>>>(php, pwp, pbp, nullptr, pqkv, nullptr, C3z, Cz);
        attn_fused_kernel<<<dim3(Tz / 64, Bz * Hz), 128, FA_SMEM>>>();
        gemm_pk_kernel<1, false><<<gCC, 256, GSMEM>>>(pyp, Wo + l * CC, bo + (size_t)l * Cz, px, px, nullptr, Cz, Cz);
        ln_pack_kernel<<<BTz, 256>>>(px, ln2_w + (size_t)l * Cz, ln2_b + (size_t)l * Cz, php);
        gemm_pk_kernel<2, false><<<gC4, 256, GSMEM>>>(php, W1 + l * C14, b1 + (size_t)l * C4z, nullptr, nullptr, pffp, C4z, Cz);
        gemm_pk_kernel<1, false><<<gCC, 256, GSMEM>>>(pffp, W2 + l * C14, b2 + (size_t)l * Cz, px, px, nullptr, Cz, C4z);
    }

    ln_pack_kernel<<<BTz, 256>>>(px, lnf_w, lnf_b, php);
    gemm_pk_kernel<3, true><<<gHead, 256, GSMEM>>>(php, head_w, nullptr, nullptr, out, nullptr, Vz, Cz);
    loss_row_kernel<<<BTz, 256>>>(out, targets);
    loss_final_kernel<<<1, 256>>>(out, out_size);
}